// round 7
// baseline (speedup 1.0000x reference)
#include <cuda_runtime.h>
#include <cstdint>

#define Tt 512
#define Bb 64
#define Ee 512
#define Hh 1024
#define Oo 512
#define NCTA 128
#define WSTRIDE 1032            // 1024 + 8 pad: kills LDS bank conflicts across cc
#define WTILE (16 * WSTRIDE)    // one 16-row weight slice
#define SMEM_BYTES (3 * WTILE * 4)

// ---------------- device scratch (static: no allocations allowed) ----------------
__device__ float g_xp[Tt * Bb * Hh];      // (t, b, h) input projections
__device__ float g_h0[2][Bb * Hh];        // layer-0 hidden ping-pong
__device__ float g_h1[2][Bb * Hh];        // layer-1 hidden ping-pong
__device__ unsigned int g_bar;            // global barrier arrival counter

// ---------------- packed f32x2 helpers (FFMA2: 2x fp32 throughput) ----------------
__device__ __forceinline__ void ffma2(unsigned long long& d, unsigned long long a, unsigned long long b) {
    asm("fma.rn.f32x2 %0, %1, %2, %0;" : "+l"(d) : "l"(a), "l"(b));
}
__device__ __forceinline__ unsigned long long pack2(float x, float y) {
    unsigned long long r; asm("mov.b64 %0, {%1, %2};" : "=l"(r) : "f"(x), "f"(y)); return r;
}
__device__ __forceinline__ float2 unpack2(unsigned long long v) {
    float2 f; asm("mov.b64 {%0, %1}, %2;" : "=f"(f.x), "=f"(f.y) : "l"(v)); return f;
}

// ---------------- init: reset barrier, load initial hidden state ----------------
__global__ void init_kernel(const float* __restrict__ h0in) {
    int idx = blockIdx.x * blockDim.x + threadIdx.x;
    if (idx == 0) g_bar = 0;
    for (int i = idx; i < Bb * Hh; i += gridDim.x * blockDim.x) {
        g_h0[0][i] = h0in[i];
        g_h1[0][i] = h0in[Bb * Hh + i];
    }
}

// ---------------- xp = embeddings @ W_ih0^T + b_ih0, stored as (t,b,h) ----------------
__global__ __launch_bounds__(256) void xp_gemm(const float* __restrict__ emb,
                                               const float* __restrict__ W,
                                               const float* __restrict__ bias) {
    __shared__ __align__(16) float As[16 * 132];
    __shared__ __align__(16) float Bs[16 * 68];
    const int tid = threadIdx.x;
    const int tx = tid & 15;
    const int ty = tid >> 4;
    const int m0 = blockIdx.y * 128;
    const int n0 = blockIdx.x * 64;

    unsigned long long acc[4][4];
#pragma unroll
    for (int i = 0; i < 4; i++)
#pragma unroll
        for (int j = 0; j < 4; j++) acc[i][j] = 0ull;

    for (int k0 = 0; k0 < Ee; k0 += 16) {
#pragma unroll
        for (int rep = 0; rep < 2; rep++) {
            int f = tid + rep * 256;
            int m_l = f >> 2, kk = (f & 3) * 4;
            int m = m0 + m_l;
            int b = m & 63, t = m >> 6;
            const float4 v = *(const float4*)(emb + ((size_t)b * Tt + t) * Ee + k0 + kk);
            As[(kk + 0) * 132 + m_l] = v.x;
            As[(kk + 1) * 132 + m_l] = v.y;
            As[(kk + 2) * 132 + m_l] = v.z;
            As[(kk + 3) * 132 + m_l] = v.w;
        }
        {
            int n_l = tid >> 2, kk = (tid & 3) * 4;
            const float4 v = *(const float4*)(W + (size_t)(n0 + n_l) * Ee + k0 + kk);
            Bs[(kk + 0) * 68 + n_l] = v.x;
            Bs[(kk + 1) * 68 + n_l] = v.y;
            Bs[(kk + 2) * 68 + n_l] = v.z;
            Bs[(kk + 3) * 68 + n_l] = v.w;
        }
        __syncthreads();
#pragma unroll
        for (int k = 0; k < 16; k++) {
            ulonglong2 aA = *(const ulonglong2*)&As[k * 132 + ty * 8];
            ulonglong2 aB = *(const ulonglong2*)&As[k * 132 + ty * 8 + 4];
            float4 bv = *(const float4*)&Bs[k * 68 + tx * 4];
            unsigned long long bd0 = pack2(bv.x, bv.x);
            unsigned long long bd1 = pack2(bv.y, bv.y);
            unsigned long long bd2 = pack2(bv.z, bv.z);
            unsigned long long bd3 = pack2(bv.w, bv.w);
            ffma2(acc[0][0], aA.x, bd0); ffma2(acc[0][1], aA.x, bd1);
            ffma2(acc[0][2], aA.x, bd2); ffma2(acc[0][3], aA.x, bd3);
            ffma2(acc[1][0], aA.y, bd0); ffma2(acc[1][1], aA.y, bd1);
            ffma2(acc[1][2], aA.y, bd2); ffma2(acc[1][3], aA.y, bd3);
            ffma2(acc[2][0], aB.x, bd0); ffma2(acc[2][1], aB.x, bd1);
            ffma2(acc[2][2], aB.x, bd2); ffma2(acc[2][3], aB.x, bd3);
            ffma2(acc[3][0], aB.y, bd0); ffma2(acc[3][1], aB.y, bd1);
            ffma2(acc[3][2], aB.y, bd2); ffma2(acc[3][3], aB.y, bd3);
        }
        __syncthreads();
    }
#pragma unroll
    for (int i2 = 0; i2 < 4; i2++) {
#pragma unroll
        for (int j = 0; j < 4; j++) {
            float2 v = unpack2(acc[i2][j]);
            int m = m0 + ty * 8 + i2 * 2;
            int n = n0 + tx * 4 + j;
            float bb = bias[n];
            g_xp[(size_t)m * Hh + n]       = v.x + bb;
            g_xp[(size_t)(m + 1) * Hh + n] = v.y + bb;
        }
    }
}

// ---------------- persistent recurrent kernel helpers ----------------
// Dot of 4 A-rows (r0, r0+8, r0+16, r0+24, read from L2 via ldcg) against one
// smem-resident weight row (Ws, stride-free pointer to this thread's column row).
__device__ __forceinline__ float4 dot4(const float* __restrict__ A, const float* __restrict__ Ws, int r0) {
    unsigned long long a0 = 0ull, a1 = 0ull, a2 = 0ull, a3 = 0ull;
    const float* p0 = A + (size_t)r0 * Hh;
#pragma unroll 8
    for (int k = 0; k < Hh; k += 4) {
        float4 w  = *(const float4*)(Ws + k);
        float4 v0 = __ldcg((const float4*)(p0 + k));
        float4 v1 = __ldcg((const float4*)(p0 + 8 * Hh + k));
        float4 v2 = __ldcg((const float4*)(p0 + 16 * Hh + k));
        float4 v3 = __ldcg((const float4*)(p0 + 24 * Hh + k));
        unsigned long long w01 = pack2(w.x, w.y), w23 = pack2(w.z, w.w);
        ffma2(a0, pack2(v0.x, v0.y), w01); ffma2(a0, pack2(v0.z, v0.w), w23);
        ffma2(a1, pack2(v1.x, v1.y), w01); ffma2(a1, pack2(v1.z, v1.w), w23);
        ffma2(a2, pack2(v2.x, v2.y), w01); ffma2(a2, pack2(v2.z, v2.w), w23);
        ffma2(a3, pack2(v3.x, v3.y), w01); ffma2(a3, pack2(v3.z, v3.w), w23);
    }
    float2 f0 = unpack2(a0), f1 = unpack2(a1), f2 = unpack2(a2), f3 = unpack2(a3);
    return make_float4(f0.x + f0.y, f1.x + f1.y, f2.x + f2.y, f3.x + f3.y);
}

// Dot of 2 A-rows (r0, r0+8) against one global weight row (W_out stays in L2).
__device__ __forceinline__ float2 dot2(const float* __restrict__ A, const float* __restrict__ Wg, int r0) {
    unsigned long long a0 = 0ull, a1 = 0ull;
    const float* p0 = A + (size_t)r0 * Hh;
#pragma unroll 8
    for (int k = 0; k < Hh; k += 4) {
        float4 w  = __ldcg((const float4*)(Wg + k));
        float4 v0 = __ldcg((const float4*)(p0 + k));
        float4 v1 = __ldcg((const float4*)(p0 + 8 * Hh + k));
        unsigned long long w01 = pack2(w.x, w.y), w23 = pack2(w.z, w.w);
        ffma2(a0, pack2(v0.x, v0.y), w01); ffma2(a0, pack2(v0.z, v0.w), w23);
        ffma2(a1, pack2(v1.x, v1.y), w01); ffma2(a1, pack2(v1.z, v1.w), w23);
    }
    float2 f0 = unpack2(a0), f1 = unpack2(a1);
    return make_float2(f0.x + f0.y, f1.x + f1.y);
}

__device__ __forceinline__ void gridbar(unsigned int gen) {
    __syncthreads();
    if (threadIdx.x == 0) {
        __threadfence();
        atomicAdd(&g_bar, 1u);
        const unsigned int target = gen * NCTA;
        while (*(volatile unsigned int*)&g_bar < target) { __nanosleep(32); }
        __threadfence();
    }
    __syncthreads();
}

// ---------------- persistent recurrent kernel ----------------
// 128 CTAs x 128 threads. CTA i statically owns:
//   h-tile:  rows b0..b0+31 (b0=(i&1)*32), cols c0..c0+15 (c0=(i>>1)*16)
//   out-tile: rows bo0..bo0+15 (bo0=(i&3)*16), cols co0..co0+15 (co0=(i>>2)*16)
// Thread (bq=tid&7, cc=tid>>3) owns rows bq+{0,8,16,24} (or bq+{0,8}) of col cc.
// W_hh0/W_ih1/W_hh1 slices live in smem for the whole kernel.
__global__ void __launch_bounds__(128, 1) rnn_persist(
    const float* __restrict__ W_hh0, const float* __restrict__ b_hh0,
    const float* __restrict__ W_ih1, const float* __restrict__ b_ih1,
    const float* __restrict__ W_hh1, const float* __restrict__ b_hh1,
    const float* __restrict__ W_out, const float* __restrict__ b_out,
    float* __restrict__ out) {
    extern __shared__ float Wsm[];
    const int tid = threadIdx.x;
    const int bq = tid & 7;
    const int cc = tid >> 3;
    const int i  = blockIdx.x;
    const int b0 = (i & 1) * 32, c0 = (i >> 1) * 16;
    const int bo0 = (i & 3) * 16, co0 = (i >> 2) * 16;

    // ---- one-time weight preload into smem (padded stride) ----
    {
        const float* s0 = W_hh0 + (size_t)c0 * Hh;
        const float* s1 = W_ih1 + (size_t)c0 * Hh;
        const float* s2 = W_hh1 + (size_t)c0 * Hh;
        for (int idx = tid; idx < 16 * (Hh / 4); idx += 128) {
            int row = idx >> 8, k4 = (idx & 255) * 4;
            *(float4*)&Wsm[0 * WTILE + row * WSTRIDE + k4] = *(const float4*)(s0 + (size_t)row * Hh + k4);
            *(float4*)&Wsm[1 * WTILE + row * WSTRIDE + k4] = *(const float4*)(s1 + (size_t)row * Hh + k4);
            *(float4*)&Wsm[2 * WTILE + row * WSTRIDE + k4] = *(const float4*)(s2 + (size_t)row * Hh + k4);
        }
    }
    const float bias0 = b_hh0[c0 + cc];
    const float bias1 = b_ih1[c0 + cc] + b_hh1[c0 + cc];
    const float biasO = b_out[co0 + cc];
    const float* Ws0 = Wsm + 0 * WTILE + cc * WSTRIDE;
    const float* Ws1 = Wsm + 1 * WTILE + cc * WSTRIDE;
    const float* Ws2 = Wsm + 2 * WTILE + cc * WSTRIDE;
    const float* WoG = W_out + (size_t)(co0 + cc) * Hh;
    __syncthreads();

    int p = 0;
    unsigned int gen = 0;

    for (int t = 0; t < Tt; t++) {
        // ---- Phase 1: h0n(t) tile + out(t-1) tile ----
        {
            const float* xpt = g_xp + ((size_t)t * Bb + b0 + bq) * Hh + (c0 + cc);
            float x0 = __ldcs(xpt);
            float x1 = __ldcs(xpt + 8 * Hh);
            float x2 = __ldcs(xpt + 16 * Hh);
            float x3 = __ldcs(xpt + 24 * Hh);

            float4 d = dot4(g_h0[p], Ws0, b0 + bq);
            float* dst = g_h0[1 - p] + (size_t)(b0 + bq) * Hh + (c0 + cc);
            __stcg(dst,            tanhf(d.x + x0 + bias0));
            __stcg(dst + 8 * Hh,   tanhf(d.y + x1 + bias0));
            __stcg(dst + 16 * Hh,  tanhf(d.z + x2 + bias0));
            __stcg(dst + 24 * Hh,  tanhf(d.w + x3 + bias0));

            if (t > 0) {
                float2 o = dot2(g_h1[p], WoG, bo0 + bq);
                out[((size_t)(bo0 + bq) * Tt + (t - 1)) * Oo + (co0 + cc)]     = o.x + biasO;
                out[((size_t)(bo0 + bq + 8) * Tt + (t - 1)) * Oo + (co0 + cc)] = o.y + biasO;
            }
        }
        gridbar(++gen);

        // ---- Phase 2: h1n(t) = tanh(h0n @ W_ih1^T + h1 @ W_hh1^T + biases) ----
        {
            float4 d1 = dot4(g_h0[1 - p], Ws1, b0 + bq);
            float4 d2 = dot4(g_h1[p],     Ws2, b0 + bq);
            float* dst = g_h1[1 - p] + (size_t)(b0 + bq) * Hh + (c0 + cc);
            __stcg(dst,            tanhf(d1.x + d2.x + bias1));
            __stcg(dst + 8 * Hh,   tanhf(d1.y + d2.y + bias1));
            __stcg(dst + 16 * Hh,  tanhf(d1.z + d2.z + bias1));
            __stcg(dst + 24 * Hh,  tanhf(d1.w + d2.w + bias1));
        }
        gridbar(++gen);
        p ^= 1;
    }

    // ---- tail: out(T-1) from final h1 (in g_h1[p]) ----
    {
        float2 o = dot2(g_h1[p], WoG, bo0 + bq);
        out[((size_t)(bo0 + bq) * Tt + (Tt - 1)) * Oo + (co0 + cc)]     = o.x + biasO;
        out[((size_t)(bo0 + bq + 8) * Tt + (Tt - 1)) * Oo + (co0 + cc)] = o.y + biasO;
    }
}

// ---------------- launch ----------------
extern "C" void kernel_launch(void* const* d_in, const int* in_sizes, int n_in,
                              void* d_out, int out_size) {
    const float* emb   = (const float*)d_in[0];
    const float* h0    = (const float*)d_in[1];
    const float* W_ih0 = (const float*)d_in[2];
    const float* b_ih0 = (const float*)d_in[3];
    const float* W_ih1 = (const float*)d_in[4];
    const float* b_ih1 = (const float*)d_in[5];
    const float* W_hh0 = (const float*)d_in[6];
    const float* b_hh0 = (const float*)d_in[7];
    const float* W_hh1 = (const float*)d_in[8];
    const float* b_hh1 = (const float*)d_in[9];
    const float* W_out = (const float*)d_in[10];
    const float* b_out = (const float*)d_in[11];
    float* out = (float*)d_out;

    static bool attr_set = false;
    if (!attr_set) {
        cudaFuncSetAttribute(rnn_persist, cudaFuncAttributeMaxDynamicSharedMemorySize, SMEM_BYTES);
        attr_set = true;
    }

    init_kernel<<<128, 256>>>(h0);
    xp_gemm<<<dim3(Hh / 64, (Tt * Bb) / 128), 256>>>(emb, W_ih0, b_ih0);
    rnn_persist<<<NCTA, 128, SMEM_BYTES>>>(W_hh0, b_hh0, W_ih1, b_ih1, W_hh1, b_hh1,
                                           W_out, b_out, out);
}

// round 8
// speedup vs baseline: 8.6241x; 8.6241x over previous
#include <cuda_runtime.h>
#include <cstdint>

#define Tt 512
#define Bb 64
#define Ee 512
#define Hh 1024
#define Oo 512
#define NCTA 128
#define WSTRIDE 1032                 // floats; 1024+8 pad -> conflict-free W rows
#define WTILEF (16 * WSTRIDE)        // floats per 16-row weight slice
#define ASTRIDE 132                  // floats; 128+4 pad -> conflict-free A rows
#define ABUFF (32 * ASTRIDE)         // floats per A staging buffer
#define SMEM_FLOATS (3 * WTILEF + 2 * ABUFF)
#define SMEM_BYTES (SMEM_FLOATS * 4) // 231,936 B <= 227KB cap

// ---------------- device scratch (static: no allocations allowed) ----------------
__device__ float g_xp[Tt * Bb * Hh];      // (t, b, h) input projections
__device__ float g_h0[2][Bb * Hh];        // layer-0 hidden ping-pong
__device__ float g_h1[2][Bb * Hh];        // layer-1 hidden ping-pong
__device__ unsigned int g_bar;            // global barrier arrival counter

// ---------------- packed f32x2 helpers ----------------
__device__ __forceinline__ void ffma2(unsigned long long& d, unsigned long long a, unsigned long long b) {
    asm("fma.rn.f32x2 %0, %1, %2, %0;" : "+l"(d) : "l"(a), "l"(b));
}
__device__ __forceinline__ unsigned long long pack2(float x, float y) {
    unsigned long long r; asm("mov.b64 %0, {%1, %2};" : "=l"(r) : "f"(x), "f"(y)); return r;
}
__device__ __forceinline__ float2 unpack2(unsigned long long v) {
    float2 f; asm("mov.b64 {%0, %1}, %2;" : "=f"(f.x), "=f"(f.y) : "l"(v)); return f;
}
__device__ __forceinline__ float redsum(unsigned long long v) {
    float2 f = unpack2(v); return f.x + f.y;
}

// ---------------- cp.async helpers (.cg = L2-only, avoids stale L1 on ping-pong) --
__device__ __forceinline__ void cpasync16(void* sdst, const void* gsrc) {
    unsigned s = (unsigned)__cvta_generic_to_shared(sdst);
    asm volatile("cp.async.cg.shared.global [%0], [%1], 16;" :: "r"(s), "l"(gsrc));
}
__device__ __forceinline__ void cp_commit() { asm volatile("cp.async.commit_group;"); }
__device__ __forceinline__ void cp_wait1()  { asm volatile("cp.async.wait_group 1;"); }
__device__ __forceinline__ void cp_wait0()  { asm volatile("cp.async.wait_group 0;"); }

// ---------------- init ----------------
__global__ void init_kernel(const float* __restrict__ h0in) {
    int idx = blockIdx.x * blockDim.x + threadIdx.x;
    if (idx == 0) g_bar = 0;
    for (int i = idx; i < Bb * Hh; i += gridDim.x * blockDim.x) {
        g_h0[0][i] = h0in[i];
        g_h1[0][i] = h0in[Bb * Hh + i];
    }
}

// ---------------- xp = embeddings @ W_ih0^T + b_ih0, stored (t,b,h) ----------------
__global__ __launch_bounds__(256) void xp_gemm(const float* __restrict__ emb,
                                               const float* __restrict__ W,
                                               const float* __restrict__ bias) {
    __shared__ __align__(16) float As[16 * 132];
    __shared__ __align__(16) float Bs[16 * 68];
    const int tid = threadIdx.x;
    const int tx = tid & 15;
    const int ty = tid >> 4;
    const int m0 = blockIdx.y * 128;
    const int n0 = blockIdx.x * 64;

    unsigned long long acc[4][4];
#pragma unroll
    for (int i = 0; i < 4; i++)
#pragma unroll
        for (int j = 0; j < 4; j++) acc[i][j] = 0ull;

    for (int k0 = 0; k0 < Ee; k0 += 16) {
#pragma unroll
        for (int rep = 0; rep < 2; rep++) {
            int f = tid + rep * 256;
            int m_l = f >> 2, kk = (f & 3) * 4;
            int m = m0 + m_l;
            int b = m & 63, t = m >> 6;
            const float4 v = *(const float4*)(emb + ((size_t)b * Tt + t) * Ee + k0 + kk);
            As[(kk + 0) * 132 + m_l] = v.x;
            As[(kk + 1) * 132 + m_l] = v.y;
            As[(kk + 2) * 132 + m_l] = v.z;
            As[(kk + 3) * 132 + m_l] = v.w;
        }
        {
            int n_l = tid >> 2, kk = (tid & 3) * 4;
            const float4 v = *(const float4*)(W + (size_t)(n0 + n_l) * Ee + k0 + kk);
            Bs[(kk + 0) * 68 + n_l] = v.x;
            Bs[(kk + 1) * 68 + n_l] = v.y;
            Bs[(kk + 2) * 68 + n_l] = v.z;
            Bs[(kk + 3) * 68 + n_l] = v.w;
        }
        __syncthreads();
#pragma unroll
        for (int k = 0; k < 16; k++) {
            ulonglong2 aA = *(const ulonglong2*)&As[k * 132 + ty * 8];
            ulonglong2 aB = *(const ulonglong2*)&As[k * 132 + ty * 8 + 4];
            float4 bv = *(const float4*)&Bs[k * 68 + tx * 4];
            unsigned long long bd0 = pack2(bv.x, bv.x);
            unsigned long long bd1 = pack2(bv.y, bv.y);
            unsigned long long bd2 = pack2(bv.z, bv.z);
            unsigned long long bd3 = pack2(bv.w, bv.w);
            ffma2(acc[0][0], aA.x, bd0); ffma2(acc[0][1], aA.x, bd1);
            ffma2(acc[0][2], aA.x, bd2); ffma2(acc[0][3], aA.x, bd3);
            ffma2(acc[1][0], aA.y, bd0); ffma2(acc[1][1], aA.y, bd1);
            ffma2(acc[1][2], aA.y, bd2); ffma2(acc[1][3], aA.y, bd3);
            ffma2(acc[2][0], aB.x, bd0); ffma2(acc[2][1], aB.x, bd1);
            ffma2(acc[2][2], aB.x, bd2); ffma2(acc[2][3], aB.x, bd3);
            ffma2(acc[3][0], aB.y, bd0); ffma2(acc[3][1], aB.y, bd1);
            ffma2(acc[3][2], aB.y, bd2); ffma2(acc[3][3], aB.y, bd3);
        }
        __syncthreads();
    }
#pragma unroll
    for (int i2 = 0; i2 < 4; i2++) {
#pragma unroll
        for (int j = 0; j < 4; j++) {
            float2 v = unpack2(acc[i2][j]);
            int m = m0 + ty * 8 + i2 * 2;
            int n = n0 + tx * 4 + j;
            float bb = bias[n];
            g_xp[(size_t)m * Hh + n]       = v.x + bb;
            g_xp[(size_t)(m + 1) * Hh + n] = v.y + bb;
        }
    }
}

// ---------------- staging: 32 rows x 128 k, coalesced 16B cp.async ----------------
__device__ __forceinline__ void stageA32(float* dst, const float* __restrict__ Ag,
                                         int chunk, int tid) {
#pragma unroll
    for (int i = 0; i < 4; i++) {
        int idx = tid + i * 256;
        int row = idx >> 5, kq = idx & 31;
        cpasync16(dst + row * ASTRIDE + kq * 4,
                  Ag + (size_t)row * Hh + chunk * 128 + kq * 4);
    }
}
// staging for dot2: rows 0-15 = A2 (16 rows), rows 16-31 = W slab (16 rows)
__device__ __forceinline__ void stageAW(float* dst, const float* __restrict__ A2g,
                                        const float* __restrict__ Wg, int chunk, int tid) {
#pragma unroll
    for (int i = 0; i < 4; i++) {
        int idx = tid + i * 256;
        if (idx < 512) {
            int row = idx >> 5, kq = idx & 31;
            cpasync16(dst + row * ASTRIDE + kq * 4,
                      A2g + (size_t)row * Hh + chunk * 128 + kq * 4);
        } else {
            int j = idx - 512;
            int row = j >> 5, kq = j & 31;
            cpasync16(dst + (16 + row) * ASTRIDE + kq * 4,
                      Wg + (size_t)row * Hh + chunk * 128 + kq * 4);
        }
    }
}

// dot of 4 owned rows (bq,+8,+16,+24) vs smem weight row; this thread covers its kg K-half
__device__ __forceinline__ void dot4_chunked(const float* __restrict__ Ag,
                                             const float* __restrict__ Wrow,
                                             float* Abuf, int tid, int bq, int kg,
                                             unsigned long long acc[4]) {
    stageA32(Abuf, Ag, 0, tid);
    cp_commit();
    for (int c = 0; c < 8; c++) {
        if (c < 7) { stageA32(Abuf + ((c + 1) & 1) * ABUFF, Ag, c + 1, tid); cp_commit(); cp_wait1(); }
        else cp_wait0();
        __syncthreads();
        const float* Ab = Abuf + (c & 1) * ABUFF + kg * 64;
        const float* Wp = Wrow + c * 128 + kg * 64;
#pragma unroll
        for (int q = 0; q < 16; q++) {
            float4 w  = *(const float4*)(Wp + q * 4);
            float4 a0 = *(const float4*)(Ab + (bq     ) * ASTRIDE + q * 4);
            float4 a1 = *(const float4*)(Ab + (bq +  8) * ASTRIDE + q * 4);
            float4 a2 = *(const float4*)(Ab + (bq + 16) * ASTRIDE + q * 4);
            float4 a3 = *(const float4*)(Ab + (bq + 24) * ASTRIDE + q * 4);
            unsigned long long w01 = pack2(w.x, w.y), w23 = pack2(w.z, w.w);
            ffma2(acc[0], pack2(a0.x, a0.y), w01); ffma2(acc[0], pack2(a0.z, a0.w), w23);
            ffma2(acc[1], pack2(a1.x, a1.y), w01); ffma2(acc[1], pack2(a1.z, a1.w), w23);
            ffma2(acc[2], pack2(a2.x, a2.y), w01); ffma2(acc[2], pack2(a2.z, a2.w), w23);
            ffma2(acc[3], pack2(a3.x, a3.y), w01); ffma2(acc[3], pack2(a3.z, a3.w), w23);
        }
        __syncthreads();
    }
}

// dot of 2 owned rows (bq, bq+8 of a 16-row tile) vs streamed W slab (rows 16-31 of buffer)
__device__ __forceinline__ void dot2_chunked(const float* __restrict__ A2g,
                                             const float* __restrict__ Wg,
                                             float* Abuf, int tid, int bq, int cc, int kg,
                                             unsigned long long acc[2]) {
    stageAW(Abuf, A2g, Wg, 0, tid);
    cp_commit();
    for (int c = 0; c < 8; c++) {
        if (c < 7) { stageAW(Abuf + ((c + 1) & 1) * ABUFF, A2g, Wg, c + 1, tid); cp_commit(); cp_wait1(); }
        else cp_wait0();
        __syncthreads();
        const float* Ab = Abuf + (c & 1) * ABUFF + kg * 64;
#pragma unroll
        for (int q = 0; q < 16; q++) {
            float4 w  = *(const float4*)(Ab + (16 + cc) * ASTRIDE + q * 4);
            float4 a0 = *(const float4*)(Ab + (bq     ) * ASTRIDE + q * 4);
            float4 a1 = *(const float4*)(Ab + (bq +  8) * ASTRIDE + q * 4);
            unsigned long long w01 = pack2(w.x, w.y), w23 = pack2(w.z, w.w);
            ffma2(acc[0], pack2(a0.x, a0.y), w01); ffma2(acc[0], pack2(a0.z, a0.w), w23);
            ffma2(acc[1], pack2(a1.x, a1.y), w01); ffma2(acc[1], pack2(a1.z, a1.w), w23);
        }
        __syncthreads();
    }
}

__device__ __forceinline__ void gridbar(unsigned int gen) {
    __syncthreads();
    if (threadIdx.x == 0) {
        __threadfence();
        atomicAdd(&g_bar, 1u);
        const unsigned int target = gen * NCTA;
        while (*(volatile unsigned int*)&g_bar < target) { __nanosleep(32); }
        __threadfence();
    }
    __syncthreads();
}

// ---------------- persistent recurrent kernel ----------------
// 128 CTAs x 256 threads. CTA i owns h-tile rows b0..b0+31 x cols c0..c0+15 and
// out-tile rows bo0..bo0+15 x cols co0..co0+15. Thread (bq=tid&7, cc=(tid>>3)&15,
// kg=tid>>7) covers K-half kg; halves reduced through smem at phase end.
__global__ void __launch_bounds__(256, 1) rnn_persist(
    const float* __restrict__ W_hh0, const float* __restrict__ b_hh0,
    const float* __restrict__ W_ih1, const float* __restrict__ b_ih1,
    const float* __restrict__ W_hh1, const float* __restrict__ b_hh1,
    const float* __restrict__ W_out, const float* __restrict__ b_out,
    float* __restrict__ out) {
    extern __shared__ __align__(16) float Wsm[];
    float* Abuf = Wsm + 3 * WTILEF;

    const int tid = threadIdx.x;
    const int bq = tid & 7;
    const int cc = (tid >> 3) & 15;
    const int kg = tid >> 7;
    const int i  = blockIdx.x;
    const int b0 = (i & 1) * 32, c0 = (i >> 1) * 16;
    const int bo0 = (i & 3) * 16, co0 = (i >> 2) * 16;

    // ---- one-time weight preload (padded stride) ----
    {
        const float* s0 = W_hh0 + (size_t)c0 * Hh;
        const float* s1 = W_ih1 + (size_t)c0 * Hh;
        const float* s2 = W_hh1 + (size_t)c0 * Hh;
        for (int idx = tid; idx < 16 * (Hh / 4); idx += 256) {
            int row = idx >> 8, k4 = (idx & 255) * 4;
            *(float4*)&Wsm[0 * WTILEF + row * WSTRIDE + k4] = *(const float4*)(s0 + (size_t)row * Hh + k4);
            *(float4*)&Wsm[1 * WTILEF + row * WSTRIDE + k4] = *(const float4*)(s1 + (size_t)row * Hh + k4);
            *(float4*)&Wsm[2 * WTILEF + row * WSTRIDE + k4] = *(const float4*)(s2 + (size_t)row * Hh + k4);
        }
    }
    const float bias0 = b_hh0[c0 + cc];
    const float bias1 = b_ih1[c0 + cc] + b_hh1[c0 + cc];
    const float biasO = b_out[co0 + cc];
    const float* Ws0 = Wsm + 0 * WTILEF + cc * WSTRIDE;
    const float* Ws1 = Wsm + 1 * WTILEF + cc * WSTRIDE;
    const float* Ws2 = Wsm + 2 * WTILEF + cc * WSTRIDE;
    const float* WoG = W_out + (size_t)co0 * Hh;   // 16-row slab, streamed per step
    __syncthreads();

    int p = 0;
    unsigned int gen = 0;

    for (int t = 0; t < Tt; t++) {
        // ================= Phase 1: h0n(t) tile + out(t-1) tile =================
        // prefetch xp early (DRAM latency overlaps the dot)
        const float* xpt = g_xp + ((size_t)t * Bb + b0 + bq) * Hh + (c0 + cc);
        float x0 = __ldcs(xpt);
        float x1 = __ldcs(xpt + 8 * Hh);
        float x2 = __ldcs(xpt + 16 * Hh);
        float x3 = __ldcs(xpt + 24 * Hh);

        unsigned long long a4[4] = {0ull, 0ull, 0ull, 0ull};
        dot4_chunked(g_h0[p] + (size_t)b0 * Hh, Ws0, Abuf, tid, bq, kg, a4);

        unsigned long long a2[2] = {0ull, 0ull};
        if (t > 0)   // uniform across grid: safe around inner __syncthreads
            dot2_chunked(g_h1[p] + (size_t)bo0 * Hh, WoG, Abuf, tid, bq, cc, kg, a2);

        // ---- cross-kg reduction via smem (Abuf is idle now) ----
        {
            float s0v = redsum(a4[0]), s1v = redsum(a4[1]);
            float s2v = redsum(a4[2]), s3v = redsum(a4[3]);
            float o0 = redsum(a2[0]), o1 = redsum(a2[1]);
            float* red = Abuf;
            __syncthreads();
            if (kg) {
                float* r = red + (tid - 128) * 8;
                r[0] = s0v; r[1] = s1v; r[2] = s2v; r[3] = s3v; r[4] = o0; r[5] = o1;
            }
            __syncthreads();
            if (!kg) {
                const float* r = red + tid * 8;
                s0v += r[0]; s1v += r[1]; s2v += r[2]; s3v += r[3];
                float* dst = g_h0[1 - p] + (size_t)(b0 + bq) * Hh + (c0 + cc);
                __stcg(dst,           tanhf(s0v + x0 + bias0));
                __stcg(dst + 8 * Hh,  tanhf(s1v + x1 + bias0));
                __stcg(dst + 16 * Hh, tanhf(s2v + x2 + bias0));
                __stcg(dst + 24 * Hh, tanhf(s3v + x3 + bias0));
                if (t > 0) {
                    out[((size_t)(bo0 + bq) * Tt + (t - 1)) * Oo + (co0 + cc)]     = o0 + r[4] + biasO;
                    out[((size_t)(bo0 + bq + 8) * Tt + (t - 1)) * Oo + (co0 + cc)] = o1 + r[5] + biasO;
                }
            }
        }
        gridbar(++gen);

        // ================= Phase 2: h1n(t) = tanh(h0n@W_ih1^T + h1@W_hh1^T + b) =================
        {
            unsigned long long acc[4] = {0ull, 0ull, 0ull, 0ull};
            dot4_chunked(g_h0[1 - p] + (size_t)b0 * Hh, Ws1, Abuf, tid, bq, kg, acc);
            dot4_chunked(g_h1[p]     + (size_t)b0 * Hh, Ws2, Abuf, tid, bq, kg, acc);

            float s0v = redsum(acc[0]), s1v = redsum(acc[1]);
            float s2v = redsum(acc[2]), s3v = redsum(acc[3]);
            float* red = Abuf;
            __syncthreads();
            if (kg) {
                float* r = red + (tid - 128) * 8;
                r[0] = s0v; r[1] = s1v; r[2] = s2v; r[3] = s3v;
            }
            __syncthreads();
            if (!kg) {
                const float* r = red + tid * 8;
                s0v += r[0]; s1v += r[1]; s2v += r[2]; s3v += r[3];
                float* dst = g_h1[1 - p] + (size_t)(b0 + bq) * Hh + (c0 + cc);
                __stcg(dst,           tanhf(s0v + bias1));
                __stcg(dst + 8 * Hh,  tanhf(s1v + bias1));
                __stcg(dst + 16 * Hh, tanhf(s2v + bias1));
                __stcg(dst + 24 * Hh, tanhf(s3v + bias1));
            }
        }
        gridbar(++gen);
        p ^= 1;
    }

    // ================= tail: out(T-1) from final h1 =================
    {
        unsigned long long a2[2] = {0ull, 0ull};
        dot2_chunked(g_h1[p] + (size_t)bo0 * Hh, WoG, Abuf, tid, bq, cc, kg, a2);
        float o0 = redsum(a2[0]), o1 = redsum(a2[1]);
        float* red = Abuf;
        __syncthreads();
        if (kg) {
            float* r = red + (tid - 128) * 8;
            r[0] = o0; r[1] = o1;
        }
        __syncthreads();
        if (!kg) {
            const float* r = red + tid * 8;
            out[((size_t)(bo0 + bq) * Tt + (Tt - 1)) * Oo + (co0 + cc)]     = o0 + r[0] + biasO;
            out[((size_t)(bo0 + bq + 8) * Tt + (Tt - 1)) * Oo + (co0 + cc)] = o1 + r[1] + biasO;
        }
    }
}

// ---------------- launch ----------------
extern "C" void kernel_launch(void* const* d_in, const int* in_sizes, int n_in,
                              void* d_out, int out_size) {
    const float* emb   = (const float*)d_in[0];
    const float* h0    = (const float*)d_in[1];
    const float* W_ih0 = (const float*)d_in[2];
    const float* b_ih0 = (const float*)d_in[3];
    const float* W_ih1 = (const float*)d_in[4];
    const float* b_ih1 = (const float*)d_in[5];
    const float* W_hh0 = (const float*)d_in[6];
    const float* b_hh0 = (const float*)d_in[7];
    const float* W_hh1 = (const float*)d_in[8];
    const float* b_hh1 = (const float*)d_in[9];
    const float* W_out = (const float*)d_in[10];
    const float* b_out = (const float*)d_in[11];
    float* out = (float*)d_out;

    static bool attr_set = false;
    if (!attr_set) {
        cudaFuncSetAttribute(rnn_persist, cudaFuncAttributeMaxDynamicSharedMemorySize, SMEM_BYTES);
        attr_set = true;
    }

    init_kernel<<<128, 256>>>(h0);
    xp_gemm<<<dim3(Hh / 64, (Tt * Bb) / 128), 256>>>(emb, W_ih0, b_ih0);
    rnn_persist<<<NCTA, 256, SMEM_BYTES>>>(W_hh0, b_hh0, W_ih1, b_ih1, W_hh1, b_hh1,
                                           W_out, b_out, out);
}

// round 11
// speedup vs baseline: 14.0729x; 1.6318x over previous
#include <cuda_runtime.h>
#include <cstdint>

#define Tt 512
#define Bb 64
#define Ee 512
#define Hh 1024
#define Oo 512
#define NCTA 128
#define WSTRIDE 1032                 // floats; 1024+8 pad
#define WTILEF (16 * WSTRIDE)        // floats per 16-row weight slice
#define ASTRIDE 132                  // floats; 128+4 pad
#define ABUFF (32 * ASTRIDE)         // floats per A staging buffer (4224)
#define SMEM_FLOATS (3 * WTILEF + 2 * ABUFF)
#define SMEM_BYTES (SMEM_FLOATS * 4) // 231,936 B (ran fine in R7)

// ---------------- device scratch ----------------
__device__ float g_xp[Tt * Bb * Hh];      // (t, b, h) input projections
__device__ float g_h0[2][Bb * Hh];        // layer-0 hidden ping-pong
__device__ float g_h1[2][Bb * Hh];        // layer-1 hidden ping-pong
__device__ unsigned int g_bar;            // global barrier arrival counter

// ---------------- packed f32x2 helpers ----------------
__device__ __forceinline__ void ffma2(unsigned long long& d, unsigned long long a, unsigned long long b) {
    asm("fma.rn.f32x2 %0, %1, %2, %0;" : "+l"(d) : "l"(a), "l"(b));
}
__device__ __forceinline__ unsigned long long pack2(float x, float y) {
    unsigned long long r; asm("mov.b64 %0, {%1, %2};" : "=l"(r) : "f"(x), "f"(y)); return r;
}
__device__ __forceinline__ float2 unpack2(unsigned long long v) {
    float2 f; asm("mov.b64 {%0, %1}, %2;" : "=f"(f.x), "=f"(f.y) : "l"(v)); return f;
}
__device__ __forceinline__ float redsum(unsigned long long v) {
    float2 f = unpack2(v); return f.x + f.y;
}

// ---------------- cp.async helpers (.cg = L2-only, avoids stale-L1 on ping-pong) --
__device__ __forceinline__ void cpasync16(void* sdst, const void* gsrc) {
    unsigned s = (unsigned)__cvta_generic_to_shared(sdst);
    asm volatile("cp.async.cg.shared.global [%0], [%1], 16;" :: "r"(s), "l"(gsrc));
}
__device__ __forceinline__ void cp_commit() { asm volatile("cp.async.commit_group;"); }
__device__ __forceinline__ void cp_wait1()  { asm volatile("cp.async.wait_group 1;"); }
__device__ __forceinline__ void cp_wait0()  { asm volatile("cp.async.wait_group 0;"); }

// ---------------- init ----------------
__global__ void init_kernel(const float* __restrict__ h0in) {
    int idx = blockIdx.x * blockDim.x + threadIdx.x;
    if (idx == 0) g_bar = 0;
    for (int i = idx; i < Bb * Hh; i += gridDim.x * blockDim.x) {
        g_h0[0][i] = h0in[i];
        g_h1[0][i] = h0in[Bb * Hh + i];
    }
}

// ---------------- xp = embeddings @ W_ih0^T + b_ih0, stored (t,b,h) ----------------
__global__ __launch_bounds__(256) void xp_gemm(const float* __restrict__ emb,
                                               const float* __restrict__ W,
                                               const float* __restrict__ bias) {
    __shared__ __align__(16) float As[16 * 132];
    __shared__ __align__(16) float Bs[16 * 68];
    const int tid = threadIdx.x;
    const int tx = tid & 15;
    const int ty = tid >> 4;
    const int m0 = blockIdx.y * 128;
    const int n0 = blockIdx.x * 64;

    unsigned long long acc[4][4];
#pragma unroll
    for (int i = 0; i < 4; i++)
#pragma unroll
        for (int j = 0; j < 4; j++) acc[i][j] = 0ull;

    for (int k0 = 0; k0 < Ee; k0 += 16) {
#pragma unroll
        for (int rep = 0; rep < 2; rep++) {
            int f = tid + rep * 256;
            int m_l = f >> 2, kk = (f & 3) * 4;
            int m = m0 + m_l;
            int b = m & 63, t = m >> 6;
            const float4 v = *(const float4*)(emb + ((size_t)b * Tt + t) * Ee + k0 + kk);
            As[(kk + 0) * 132 + m_l] = v.x;
            As[(kk + 1) * 132 + m_l] = v.y;
            As[(kk + 2) * 132 + m_l] = v.z;
            As[(kk + 3) * 132 + m_l] = v.w;
        }
        {
            int n_l = tid >> 2, kk = (tid & 3) * 4;
            const float4 v = *(const float4*)(W + (size_t)(n0 + n_l) * Ee + k0 + kk);
            Bs[(kk + 0) * 68 + n_l] = v.x;
            Bs[(kk + 1) * 68 + n_l] = v.y;
            Bs[(kk + 2) * 68 + n_l] = v.z;
            Bs[(kk + 3) * 68 + n_l] = v.w;
        }
        __syncthreads();
#pragma unroll
        for (int k = 0; k < 16; k++) {
            ulonglong2 aA = *(const ulonglong2*)&As[k * 132 + ty * 8];
            ulonglong2 aB = *(const ulonglong2*)&As[k * 132 + ty * 8 + 4];
            float4 bv = *(const float4*)&Bs[k * 68 + tx * 4];
            unsigned long long bd0 = pack2(bv.x, bv.x);
            unsigned long long bd1 = pack2(bv.y, bv.y);
            unsigned long long bd2 = pack2(bv.z, bv.z);
            unsigned long long bd3 = pack2(bv.w, bv.w);
            ffma2(acc[0][0], aA.x, bd0); ffma2(acc[0][1], aA.x, bd1);
            ffma2(acc[0][2], aA.x, bd2); ffma2(acc[0][3], aA.x, bd3);
            ffma2(acc[1][0], aA.y, bd0); ffma2(acc[1][1], aA.y, bd1);
            ffma2(acc[1][2], aA.y, bd2); ffma2(acc[1][3], aA.y, bd3);
            ffma2(acc[2][0], aB.x, bd0); ffma2(acc[2][1], aB.x, bd1);
            ffma2(acc[2][2], aB.x, bd2); ffma2(acc[2][3], aB.x, bd3);
            ffma2(acc[3][0], aB.y, bd0); ffma2(acc[3][1], aB.y, bd1);
            ffma2(acc[3][2], aB.y, bd2); ffma2(acc[3][3], aB.y, bd3);
        }
        __syncthreads();
    }
#pragma unroll
    for (int i2 = 0; i2 < 4; i2++) {
#pragma unroll
        for (int j = 0; j < 4; j++) {
            float2 v = unpack2(acc[i2][j]);
            int m = m0 + ty * 8 + i2 * 2;
            int n = n0 + tx * 4 + j;
            float bb = bias[n];
            g_xp[(size_t)m * Hh + n]       = v.x + bb;
            g_xp[(size_t)(m + 1) * Hh + n] = v.y + bb;
        }
    }
}

// ---------------- staging: 32 rows x 128 k, coalesced 16B cp.async ----------------
__device__ __forceinline__ void stageA32(float* dst, const float* __restrict__ Ag,
                                         int chunk, int tid) {
#pragma unroll
    for (int i = 0; i < 4; i++) {
        int idx = tid + i * 256;
        int row = idx >> 5, kq = idx & 31;
        cpasync16(dst + row * ASTRIDE + kq * 4,
                  Ag + (size_t)row * Hh + chunk * 128 + kq * 4);
    }
}
// staging for out-dot: rows 0-15 = h1 tile (16 rows), rows 16-31 = W_out slab (16 rows)
__device__ __forceinline__ void stageAW(float* dst, const float* __restrict__ A2g,
                                        const float* __restrict__ Wg, int chunk, int tid) {
#pragma unroll
    for (int i = 0; i < 4; i++) {
        int idx = tid + i * 256;
        if (idx < 512) {
            int row = idx >> 5, kq = idx & 31;
            cpasync16(dst + row * ASTRIDE + kq * 4,
                      A2g + (size_t)row * Hh + chunk * 128 + kq * 4);
        } else {
            int j = idx - 512;
            int row = j >> 5, kq = j & 31;
            cpasync16(dst + (16 + row) * ASTRIDE + kq * 4,
                      Wg + (size_t)row * Hh + chunk * 128 + kq * 4);
        }
    }
}

// ---------------- 4x4 register-tile dot: 32 rows x 16 cols x K=1024 -------------
// Thread (bq, ccq, kg): rows bq+{0,8,16,24}, cols ccq+{0,4,8,12}, k in [kg*16, kg*16+16)
// of each 128-k chunk. acc[r*4+j] accumulates packed f32x2 partial sums.
__device__ __forceinline__ void dot44(const float* __restrict__ Ag,
                                      const float* __restrict__ Wmat,
                                      float* Abuf, int tid, int bq, int ccq, int kg,
                                      unsigned long long acc[16]) {
    stageA32(Abuf, Ag, 0, tid);
    cp_commit();
    for (int c = 0; c < 8; c++) {
        if (c < 7) { stageA32(Abuf + ((c + 1) & 1) * ABUFF, Ag, c + 1, tid); cp_commit(); cp_wait1(); }
        else cp_wait0();
        __syncthreads();
        const float* Ab = Abuf + (c & 1) * ABUFF + kg * 16;
        const float* Wp = Wmat + c * 128 + kg * 16;
#pragma unroll
        for (int q = 0; q < 4; q++) {
            ulonglong2 a0 = *(const ulonglong2*)(Ab + (bq     ) * ASTRIDE + q * 4);
            ulonglong2 a1 = *(const ulonglong2*)(Ab + (bq +  8) * ASTRIDE + q * 4);
            ulonglong2 a2 = *(const ulonglong2*)(Ab + (bq + 16) * ASTRIDE + q * 4);
            ulonglong2 a3 = *(const ulonglong2*)(Ab + (bq + 24) * ASTRIDE + q * 4);
            ulonglong2 w0 = *(const ulonglong2*)(Wp + (ccq     ) * WSTRIDE + q * 4);
            ulonglong2 w1 = *(const ulonglong2*)(Wp + (ccq +  4) * WSTRIDE + q * 4);
            ulonglong2 w2 = *(const ulonglong2*)(Wp + (ccq +  8) * WSTRIDE + q * 4);
            ulonglong2 w3 = *(const ulonglong2*)(Wp + (ccq + 12) * WSTRIDE + q * 4);
            ffma2(acc[ 0], a0.x, w0.x); ffma2(acc[ 0], a0.y, w0.y);
            ffma2(acc[ 1], a0.x, w1.x); ffma2(acc[ 1], a0.y, w1.y);
            ffma2(acc[ 2], a0.x, w2.x); ffma2(acc[ 2], a0.y, w2.y);
            ffma2(acc[ 3], a0.x, w3.x); ffma2(acc[ 3], a0.y, w3.y);
            ffma2(acc[ 4], a1.x, w0.x); ffma2(acc[ 4], a1.y, w0.y);
            ffma2(acc[ 5], a1.x, w1.x); ffma2(acc[ 5], a1.y, w1.y);
            ffma2(acc[ 6], a1.x, w2.x); ffma2(acc[ 6], a1.y, w2.y);
            ffma2(acc[ 7], a1.x, w3.x); ffma2(acc[ 7], a1.y, w3.y);
            ffma2(acc[ 8], a2.x, w0.x); ffma2(acc[ 8], a2.y, w0.y);
            ffma2(acc[ 9], a2.x, w1.x); ffma2(acc[ 9], a2.y, w1.y);
            ffma2(acc[10], a2.x, w2.x); ffma2(acc[10], a2.y, w2.y);
            ffma2(acc[11], a2.x, w3.x); ffma2(acc[11], a2.y, w3.y);
            ffma2(acc[12], a3.x, w0.x); ffma2(acc[12], a3.y, w0.y);
            ffma2(acc[13], a3.x, w1.x); ffma2(acc[13], a3.y, w1.y);
            ffma2(acc[14], a3.x, w2.x); ffma2(acc[14], a3.y, w2.y);
            ffma2(acc[15], a3.x, w3.x); ffma2(acc[15], a3.y, w3.y);
        }
        __syncthreads();
    }
}

// ---------------- 2x4 register-tile out-dot: 16 rows x 16 cols x K=1024 ----------
// Thread (bq, ccq, kg): rows bq+{0,8}, cols ccq+{0,4,8,12}. W streamed in rows 16-31.
__device__ __forceinline__ void dot24(const float* __restrict__ A2g,
                                      const float* __restrict__ Wg,
                                      float* Abuf, int tid, int bq, int ccq, int kg,
                                      unsigned long long acc[8]) {
    stageAW(Abuf, A2g, Wg, 0, tid);
    cp_commit();
    for (int c = 0; c < 8; c++) {
        if (c < 7) { stageAW(Abuf + ((c + 1) & 1) * ABUFF, A2g, Wg, c + 1, tid); cp_commit(); cp_wait1(); }
        else cp_wait0();
        __syncthreads();
        const float* Ab = Abuf + (c & 1) * ABUFF + kg * 16;
#pragma unroll
        for (int q = 0; q < 4; q++) {
            ulonglong2 a0 = *(const ulonglong2*)(Ab + (bq    ) * ASTRIDE + q * 4);
            ulonglong2 a1 = *(const ulonglong2*)(Ab + (bq + 8) * ASTRIDE + q * 4);
            ulonglong2 w0 = *(const ulonglong2*)(Ab + (16 + ccq     ) * ASTRIDE + q * 4);
            ulonglong2 w1 = *(const ulonglong2*)(Ab + (16 + ccq +  4) * ASTRIDE + q * 4);
            ulonglong2 w2 = *(const ulonglong2*)(Ab + (16 + ccq +  8) * ASTRIDE + q * 4);
            ulonglong2 w3 = *(const ulonglong2*)(Ab + (16 + ccq + 12) * ASTRIDE + q * 4);
            ffma2(acc[0], a0.x, w0.x); ffma2(acc[0], a0.y, w0.y);
            ffma2(acc[1], a0.x, w1.x); ffma2(acc[1], a0.y, w1.y);
            ffma2(acc[2], a0.x, w2.x); ffma2(acc[2], a0.y, w2.y);
            ffma2(acc[3], a0.x, w3.x); ffma2(acc[3], a0.y, w3.y);
            ffma2(acc[4], a1.x, w0.x); ffma2(acc[4], a1.y, w0.y);
            ffma2(acc[5], a1.x, w1.x); ffma2(acc[5], a1.y, w1.y);
            ffma2(acc[6], a1.x, w2.x); ffma2(acc[6], a1.y, w2.y);
            ffma2(acc[7], a1.x, w3.x); ffma2(acc[7], a1.y, w3.y);
        }
        __syncthreads();
    }
}

__device__ __forceinline__ void gridbar(unsigned int gen) {
    __syncthreads();
    if (threadIdx.x == 0) {
        __threadfence();
        atomicAdd(&g_bar, 1u);
        const unsigned int target = gen * NCTA;
        while (*(volatile unsigned int*)&g_bar < target) { __nanosleep(32); }
        __threadfence();
    }
    __syncthreads();
}

// ---------------- persistent recurrent kernel ----------------
// 128 CTAs x 256 threads. CTA i owns h-tile rows b0..b0+31 x cols c0..c0+15 and
// out-tile rows bo0..bo0+15 x cols co0..co0+15.
// Thread coords: bq=tid&7, ccq=(tid>>3)&3, kg=tid>>5 (warp-uniform K-split).
__global__ void __launch_bounds__(256, 1) rnn_persist(
    const float* __restrict__ W_hh0, const float* __restrict__ b_hh0,
    const float* __restrict__ W_ih1, const float* __restrict__ b_ih1,
    const float* __restrict__ W_hh1, const float* __restrict__ b_hh1,
    const float* __restrict__ W_out, const float* __restrict__ b_out,
    float* __restrict__ out) {
    extern __shared__ __align__(16) float Wsm[];
    float* Abuf = Wsm + 3 * WTILEF;

    const int tid = threadIdx.x;
    const int bq  = tid & 7;
    const int ccq = (tid >> 3) & 3;
    const int kg  = tid >> 5;
    const int i   = blockIdx.x;
    const int b0 = (i & 1) * 32, c0 = (i >> 1) * 16;
    const int bo0 = (i & 3) * 16, co0 = (i >> 2) * 16;

    // ---- finalize maps (computed once) ----
    // h outputs: this thread finalizes slot ids 2*tid, 2*tid+1
    // slot -> (lane, i2, j): lane=slot>>4, i2=(slot>>2)&3, j=slot&3
    // row = (lane&7) + 8*i2 ; col = ((lane>>3)&3) + 4*j
    const int hs0 = 2 * tid, hs1 = 2 * tid + 1;
    const int hr0 = ((hs0 >> 4) & 7) + 8 * ((hs0 >> 2) & 3);
    const int hc0 = (((hs0 >> 4) >> 3) & 3) + 4 * (hs0 & 3);
    const int hr1 = ((hs1 >> 4) & 7) + 8 * ((hs1 >> 2) & 3);
    const int hc1 = (((hs1 >> 4) >> 3) & 3) + 4 * (hs1 & 3);
    // out outputs: this thread finalizes slot id tid: lane=tid>>3, i2=(tid>>2)&1, j=tid&3
    const int os  = tid;
    const int or0 = ((os >> 3) & 7) + 8 * ((os >> 2) & 1);
    const int oc0 = (((os >> 3) >> 3) & 3) + 4 * (os & 3);

    // ---- one-time weight preload (padded stride) ----
    {
        const float* s0 = W_hh0 + (size_t)c0 * Hh;
        const float* s1 = W_ih1 + (size_t)c0 * Hh;
        const float* s2 = W_hh1 + (size_t)c0 * Hh;
        for (int idx = tid; idx < 16 * (Hh / 4); idx += 256) {
            int row = idx >> 8, k4 = (idx & 255) * 4;
            *(float4*)&Wsm[0 * WTILEF + row * WSTRIDE + k4] = *(const float4*)(s0 + (size_t)row * Hh + k4);
            *(float4*)&Wsm[1 * WTILEF + row * WSTRIDE + k4] = *(const float4*)(s1 + (size_t)row * Hh + k4);
            *(float4*)&Wsm[2 * WTILEF + row * WSTRIDE + k4] = *(const float4*)(s2 + (size_t)row * Hh + k4);
        }
    }
    const float biasH0_0 = __ldg(b_hh0 + c0 + hc0);
    const float biasH0_1 = __ldg(b_hh0 + c0 + hc1);
    const float biasH1_0 = __ldg(b_ih1 + c0 + hc0) + __ldg(b_hh1 + c0 + hc0);
    const float biasH1_1 = __ldg(b_ih1 + c0 + hc1) + __ldg(b_hh1 + c0 + hc1);
    const float biasO    = __ldg(b_out + co0 + oc0);
    const float* WoG = W_out + (size_t)co0 * Hh;   // 16-row slab, streamed per step
    __syncthreads();

    int p = 0;
    unsigned int gen = 0;

    for (int t = 0; t < Tt; t++) {
        // ================= Phase 1: h0n(t) tile + out(t-1) tile =================
        // prefetch xp for this thread's two finalized outputs (DRAM latency hidden by dots)
        const float* xpt = g_xp + ((size_t)t * Bb + b0) * Hh + c0;
        float x0 = __ldcs(xpt + (size_t)hr0 * Hh + hc0);
        float x1 = __ldcs(xpt + (size_t)hr1 * Hh + hc1);

        unsigned long long accH[16];
#pragma unroll
        for (int z = 0; z < 16; z++) accH[z] = 0ull;
        dot44(g_h0[p] + (size_t)b0 * Hh, Wsm + 0 * WTILEF, Abuf, tid, bq, ccq, kg, accH);

        unsigned long long accO[8];
#pragma unroll
        for (int z = 0; z < 8; z++) accO[z] = 0ull;
        if (t > 0)   // uniform across grid: safe around inner __syncthreads
            dot24(g_h1[p] + (size_t)bo0 * Hh, WoG, Abuf, tid, bq, ccq, kg, accO);

        // ---- cross-kg reductions via smem (Abuf idle now) ----
        {
            float* hred = Abuf;                 // 32 lanes * 132 floats
            float* ored = Abuf + ABUFF;         // 32 lanes * 68 floats
            const int lane = tid & 31;
            __syncthreads();
#pragma unroll
            for (int z = 0; z < 16; z++)
                hred[lane * 132 + z * 8 + kg] = redsum(accH[z]);
            if (t > 0) {
#pragma unroll
                for (int z = 0; z < 8; z++)
                    ored[lane * 68 + z * 8 + kg] = redsum(accO[z]);
            }
            __syncthreads();
            // finalize h: 2 outputs per thread
            {
                const float* r0 = hred + (hs0 >> 4) * 132 + (hs0 & 15) * 8;
                const float* r1 = hred + (hs1 >> 4) * 132 + (hs1 & 15) * 8;
                float4 u0 = *(const float4*)(r0), u1 = *(const float4*)(r0 + 4);
                float4 v0 = *(const float4*)(r1), v1 = *(const float4*)(r1 + 4);
                float s0 = (u0.x + u0.y) + (u0.z + u0.w) + (u1.x + u1.y) + (u1.z + u1.w);
                float s1 = (v0.x + v0.y) + (v0.z + v0.w) + (v1.x + v1.y) + (v1.z + v1.w);
                float* dst = g_h0[1 - p] + (size_t)b0 * Hh + c0;
                __stcg(dst + (size_t)hr0 * Hh + hc0, tanhf(s0 + x0 + biasH0_0));
                __stcg(dst + (size_t)hr1 * Hh + hc1, tanhf(s1 + x1 + biasH0_1));
            }
            // finalize out(t-1): 1 output per thread
            if (t > 0) {
                const float* r = ored + (os >> 3) * 68 + (os & 7) * 8;
                float4 u0 = *(const float4*)(r), u1 = *(const float4*)(r + 4);
                float s = (u0.x + u0.y) + (u0.z + u0.w) + (u1.x + u1.y) + (u1.z + u1.w);
                out[((size_t)(bo0 + or0) * Tt + (t - 1)) * Oo + (co0 + oc0)] = s + biasO;
            }
        }
        gridbar(++gen);

        // ================= Phase 2: h1n(t) = tanh(h0n@W_ih1^T + h1@W_hh1^T + b) =================
        {
            unsigned long long acc[16];
#pragma unroll
            for (int z = 0; z < 16; z++) acc[z] = 0ull;
            dot44(g_h0[1 - p] + (size_t)b0 * Hh, Wsm + 1 * WTILEF, Abuf, tid, bq, ccq, kg, acc);
            dot44(g_h1[p]     + (size_t)b0 * Hh, Wsm + 2 * WTILEF, Abuf, tid, bq, ccq, kg, acc);

            float* hred = Abuf;
            const int lane = tid & 31;
            __syncthreads();
#pragma unroll
            for (int z = 0; z < 16; z++)
                hred[lane * 132 + z * 8 + kg] = redsum(acc[z]);
            __syncthreads();
            const float* r0 = hred + (hs0 >> 4) * 132 + (hs0 & 15) * 8;
            const float* r1 = hred + (hs1 >> 4) * 132 + (hs1 & 15) * 8;
            float4 u0 = *(const float4*)(r0), u1 = *(const float4*)(r0 + 4);
            float4 v0 = *(const float4*)(r1), v1 = *(const float4*)(r1 + 4);
            float s0 = (u0.x + u0.y) + (u0.z + u0.w) + (u1.x + u1.y) + (u1.z + u1.w);
            float s1 = (v0.x + v0.y) + (v0.z + v0.w) + (v1.x + v1.y) + (v1.z + v1.w);
            float* dst = g_h1[1 - p] + (size_t)b0 * Hh + c0;
            __stcg(dst + (size_t)hr0 * Hh + hc0, tanhf(s0 + biasH1_0));
            __stcg(dst + (size_t)hr1 * Hh + hc1, tanhf(s1 + biasH1_1));
        }
        gridbar(++gen);
        p ^= 1;
    }

    // ================= tail: out(T-1) from final h1 =================
    {
        unsigned long long accO[8];
#pragma unroll
        for (int z = 0; z < 8; z++) accO[z] = 0ull;
        dot24(g_h1[p] + (size_t)bo0 * Hh, WoG, Abuf, tid, bq, ccq, kg, accO);
        float* ored = Abuf;
        const int lane = tid & 31;
        __syncthreads();
#pragma unroll
        for (int z = 0; z < 8; z++)
            ored[lane * 68 + z * 8 + kg] = redsum(accO[z]);
        __syncthreads();
        const float* r = ored + (os >> 3) * 68 + (os & 7) * 8;
        float4 u0 = *(const float4*)(r), u1 = *(const float4*)(r + 4);
        float s = (u0.x + u0.y) + (u0.z + u0.w) + (u1.x + u1.y) + (u1.z + u1.w);
        out[((size_t)(bo0 + or0) * Tt + (Tt - 1)) * Oo + (co0 + oc0)] = s + biasO;
    }
}

// ---------------- launch ----------------
extern "C" void kernel_launch(void* const* d_in, const int* in_sizes, int n_in,
                              void* d_out, int out_size) {
    const float* emb   = (const float*)d_in[0];
    const float* h0    = (const float*)d_in[1];
    const float* W_ih0 = (const float*)d_in[2];
    const float* b_ih0 = (const float*)d_in[3];
    const float* W_ih1 = (const float*)d_in[4];
    const float* b_ih1 = (const float*)d_in[5];
    const float* W_hh0 = (const float*)d_in[6];
    const float* b_hh0 = (const float*)d_in[7];
    const float* W_hh1 = (const float*)d_in[8];
    const float* b_hh1 = (const float*)d_in[9];
    const float* W_out = (const float*)d_in[10];
    const float* b_out = (const float*)d_in[11];
    float* out = (float*)d_out;

    static bool attr_set = false;
    if (!attr_set) {
        cudaFuncSetAttribute(rnn_persist, cudaFuncAttributeMaxDynamicSharedMemorySize, SMEM_BYTES);
        attr_set = true;
    }

    init_kernel<<<128, 256>>>(h0);
    xp_gemm<<<dim3(Hh / 64, (Tt * Bb) / 128), 256>>>(emb, W_ih0, b_ih0);
    rnn_persist<<<NCTA, 256, SMEM_BYTES>>>(W_hh0, b_hh0, W_ih1, b_ih1, W_hh1, b_hh1,
                                           W_out, b_out, out);
}

// round 16
// speedup vs baseline: 15.0715x; 1.0710x over previous
#include <cuda_runtime.h>
#include <cstdint>

#define Tt 512
#define Bb 64
#define Ee 512
#define Hh 1024
#define Oo 512
#define NCTA 128
#define NTHR 512
#define WT 16384                 // floats per 16-row swizzled weight slice (16*1024)
#define ASTRIDE 132              // floats; 128+4 pad for A staging rows
#define ABUFF (32 * ASTRIDE)     // 4224 floats per staging buffer
#define REDSZ (16 * 545)         // 8720 floats reduction scratch (overlaps staging)
#define SMEM_FLOATS (3 * WT + REDSZ)
#define SMEM_BYTES (SMEM_FLOATS * 4)   // 231,488 B <= 232,448 cap

typedef unsigned long long u64;

// ---------------- device scratch ----------------
__device__ float g_xp[Tt * Bb * Hh];      // (t, b, h) input projections
__device__ float g_h0[2][Bb * Hh];        // layer-0 hidden ping-pong
__device__ float g_h1[2][Bb * Hh];        // layer-1 hidden ping-pong
__device__ unsigned int g_bar;            // global barrier arrival counter

// ---------------- packed f32x2 helpers ----------------
__device__ __forceinline__ void ffma2(u64& d, u64 a, u64 b) {
    asm("fma.rn.f32x2 %0, %1, %2, %0;" : "+l"(d) : "l"(a), "l"(b));
}
__device__ __forceinline__ u64 pack2(float x, float y) {
    u64 r; asm("mov.b64 %0, {%1, %2};" : "=l"(r) : "f"(x), "f"(y)); return r;
}
__device__ __forceinline__ float2 unpack2(u64 v) {
    float2 f; asm("mov.b64 {%0, %1}, %2;" : "=f"(f.x), "=f"(f.y) : "l"(v)); return f;
}
__device__ __forceinline__ float redsum(u64 v) {
    float2 f = unpack2(v); return f.x + f.y;
}

// ---------------- cp.async helpers (.cg = L2-only: ping-pong coherence) ----------
__device__ __forceinline__ void cpasync16(void* sdst, const void* gsrc) {
    unsigned s = (unsigned)__cvta_generic_to_shared(sdst);
    asm volatile("cp.async.cg.shared.global [%0], [%1], 16;" :: "r"(s), "l"(gsrc));
}
__device__ __forceinline__ void cp_commit() { asm volatile("cp.async.commit_group;"); }
__device__ __forceinline__ void cp_wait1()  { asm volatile("cp.async.wait_group 1;"); }
__device__ __forceinline__ void cp_wait0()  { asm volatile("cp.async.wait_group 0;"); }

// ---------------- init ----------------
__global__ void init_kernel(const float* __restrict__ h0in) {
    int idx = blockIdx.x * blockDim.x + threadIdx.x;
    if (idx == 0) g_bar = 0;
    for (int i = idx; i < Bb * Hh; i += gridDim.x * blockDim.x) {
        g_h0[0][i] = h0in[i];
        g_h1[0][i] = h0in[Bb * Hh + i];
    }
}

// ---------------- xp = embeddings @ W_ih0^T + b_ih0, stored (t,b,h) ----------------
__global__ __launch_bounds__(256) void xp_gemm(const float* __restrict__ emb,
                                               const float* __restrict__ W,
                                               const float* __restrict__ bias) {
    __shared__ __align__(16) float As[16 * 132];
    __shared__ __align__(16) float Bs[16 * 68];
    const int tid = threadIdx.x;
    const int tx = tid & 15;
    const int ty = tid >> 4;
    const int m0 = blockIdx.y * 128;
    const int n0 = blockIdx.x * 64;

    u64 acc[4][4];
#pragma unroll
    for (int i = 0; i < 4; i++)
#pragma unroll
        for (int j = 0; j < 4; j++) acc[i][j] = 0ull;

    for (int k0 = 0; k0 < Ee; k0 += 16) {
#pragma unroll
        for (int rep = 0; rep < 2; rep++) {
            int f = tid + rep * 256;
            int m_l = f >> 2, kk = (f & 3) * 4;
            int m = m0 + m_l;
            int b = m & 63, t = m >> 6;
            const float4 v = *(const float4*)(emb + ((size_t)b * Tt + t) * Ee + k0 + kk);
            As[(kk + 0) * 132 + m_l] = v.x;
            As[(kk + 1) * 132 + m_l] = v.y;
            As[(kk + 2) * 132 + m_l] = v.z;
            As[(kk + 3) * 132 + m_l] = v.w;
        }
        {
            int n_l = tid >> 2, kk = (tid & 3) * 4;
            const float4 v = *(const float4*)(W + (size_t)(n0 + n_l) * Ee + k0 + kk);
            Bs[(kk + 0) * 68 + n_l] = v.x;
            Bs[(kk + 1) * 68 + n_l] = v.y;
            Bs[(kk + 2) * 68 + n_l] = v.z;
            Bs[(kk + 3) * 68 + n_l] = v.w;
        }
        __syncthreads();
#pragma unroll
        for (int k = 0; k < 16; k++) {
            ulonglong2 aA = *(const ulonglong2*)&As[k * 132 + ty * 8];
            ulonglong2 aB = *(const ulonglong2*)&As[k * 132 + ty * 8 + 4];
            float4 bv = *(const float4*)&Bs[k * 68 + tx * 4];
            u64 bd0 = pack2(bv.x, bv.x);
            u64 bd1 = pack2(bv.y, bv.y);
            u64 bd2 = pack2(bv.z, bv.z);
            u64 bd3 = pack2(bv.w, bv.w);
            ffma2(acc[0][0], aA.x, bd0); ffma2(acc[0][1], aA.x, bd1);
            ffma2(acc[0][2], aA.x, bd2); ffma2(acc[0][3], aA.x, bd3);
            ffma2(acc[1][0], aA.y, bd0); ffma2(acc[1][1], aA.y, bd1);
            ffma2(acc[1][2], aA.y, bd2); ffma2(acc[1][3], aA.y, bd3);
            ffma2(acc[2][0], aB.x, bd0); ffma2(acc[2][1], aB.x, bd1);
            ffma2(acc[2][2], aB.x, bd2); ffma2(acc[2][3], aB.x, bd3);
            ffma2(acc[3][0], aB.y, bd0); ffma2(acc[3][1], aB.y, bd1);
            ffma2(acc[3][2], aB.y, bd2); ffma2(acc[3][3], aB.y, bd3);
        }
        __syncthreads();
    }
#pragma unroll
    for (int i2 = 0; i2 < 4; i2++) {
#pragma unroll
        for (int j = 0; j < 4; j++) {
            float2 v = unpack2(acc[i2][j]);
            int m = m0 + ty * 8 + i2 * 2;
            int n = n0 + tx * 4 + j;
            float bb = bias[n];
            g_xp[(size_t)m * Hh + n]       = v.x + bb;
            g_xp[(size_t)(m + 1) * Hh + n] = v.y + bb;
        }
    }
}

// ---------------- staging (512 threads): 32 rows x 128 k, 16B cp.async ----------
__device__ __forceinline__ void stageA32(float* dst, const float* __restrict__ Ag,
                                         int chunk, int tid) {
#pragma unroll
    for (int i = 0; i < 2; i++) {
        int idx = tid + i * 512;
        int row = idx >> 5, kq = idx & 31;
        cpasync16(dst + row * ASTRIDE + kq * 4,
                  Ag + (size_t)row * Hh + chunk * 128 + kq * 4);
    }
}
// rows 0-15 = A tile (16 rows), rows 16-31 = streamed W slab (16 rows)
__device__ __forceinline__ void stageAW(float* dst, const float* __restrict__ A2g,
                                        const float* __restrict__ Wg, int chunk, int tid) {
    {
        int row = tid >> 5, kq = tid & 31;
        cpasync16(dst + row * ASTRIDE + kq * 4,
                  A2g + (size_t)row * Hh + chunk * 128 + kq * 4);
        cpasync16(dst + (16 + row) * ASTRIDE + kq * 4,
                  Wg + (size_t)row * Hh + chunk * 128 + kq * 4);
    }
}

// ---------------- 4x4 tile dot: 32 rows x 16 cols x K=1024, W swizzled in smem ---
// thread (bq=tid&7, ccq=(tid>>3)&3, kg=tid>>5): rows bq+{0,8,16,24},
// cols ccq+{0,4,8,12}, k = c*128 + kg*8 + q*4 (q=0..1).
// Pipeline: R11-proven two-barrier form (stage next / commit / wait1, bar, compute, bar).
__device__ __forceinline__ void dot44(const float* __restrict__ Ag,
                                      const float* __restrict__ Wslice,
                                      float* scratch, int tid, int bq, int ccq, int kg,
                                      u64 acc[16]) {
    stageA32(scratch, Ag, 0, tid);
    cp_commit();
    for (int c = 0; c < 8; c++) {
        if (c < 7) { stageA32(scratch + ((c + 1) & 1) * ABUFF, Ag, c + 1, tid); cp_commit(); cp_wait1(); }
        else cp_wait0();
        __syncthreads();
        const float* Ap = scratch + (c & 1) * ABUFF + bq * ASTRIDE + kg * 8;
        const float* Wb = Wslice + ccq * 1024;
        const int qb = c * 32 + kg * 2;
#pragma unroll
        for (int q = 0; q < 2; q++) {
            const int wq = ((qb + q) ^ ccq) << 2;        // quad swizzle (key = row&3 = ccq)
            ulonglong2 w0 = *(const ulonglong2*)(Wb + wq);
            ulonglong2 w1 = *(const ulonglong2*)(Wb + 4096 + wq);
            ulonglong2 w2 = *(const ulonglong2*)(Wb + 8192 + wq);
            ulonglong2 w3 = *(const ulonglong2*)(Wb + 12288 + wq);
            ulonglong2 a0 = *(const ulonglong2*)(Ap + q * 4);
            ulonglong2 a1 = *(const ulonglong2*)(Ap + 8 * ASTRIDE + q * 4);
            ulonglong2 a2 = *(const ulonglong2*)(Ap + 16 * ASTRIDE + q * 4);
            ulonglong2 a3 = *(const ulonglong2*)(Ap + 24 * ASTRIDE + q * 4);
            ffma2(acc[ 0], a0.x, w0.x); ffma2(acc[ 0], a0.y, w0.y);
            ffma2(acc[ 1], a0.x, w1.x); ffma2(acc[ 1], a0.y, w1.y);
            ffma2(acc[ 2], a0.x, w2.x); ffma2(acc[ 2], a0.y, w2.y);
            ffma2(acc[ 3], a0.x, w3.x); ffma2(acc[ 3], a0.y, w3.y);
            ffma2(acc[ 4], a1.x, w0.x); ffma2(acc[ 4], a1.y, w0.y);
            ffma2(acc[ 5], a1.x, w1.x); ffma2(acc[ 5], a1.y, w1.y);
            ffma2(acc[ 6], a1.x, w2.x); ffma2(acc[ 6], a1.y, w2.y);
            ffma2(acc[ 7], a1.x, w3.x); ffma2(acc[ 7], a1.y, w3.y);
            ffma2(acc[ 8], a2.x, w0.x); ffma2(acc[ 8], a2.y, w0.y);
            ffma2(acc[ 9], a2.x, w1.x); ffma2(acc[ 9], a2.y, w1.y);
            ffma2(acc[10], a2.x, w2.x); ffma2(acc[10], a2.y, w2.y);
            ffma2(acc[11], a2.x, w3.x); ffma2(acc[11], a2.y, w3.y);
            ffma2(acc[12], a3.x, w0.x); ffma2(acc[12], a3.y, w0.y);
            ffma2(acc[13], a3.x, w1.x); ffma2(acc[13], a3.y, w1.y);
            ffma2(acc[14], a3.x, w2.x); ffma2(acc[14], a3.y, w2.y);
            ffma2(acc[15], a3.x, w3.x); ffma2(acc[15], a3.y, w3.y);
        }
        __syncthreads();
    }
}

// ---------------- 2x4 tile out-dot: 16 rows x 16 cols x K=1024, W streamed -------
__device__ __forceinline__ void dot24(const float* __restrict__ A2g,
                                      const float* __restrict__ Wg,
                                      float* scratch, int tid, int bq, int ccq, int kg,
                                      u64 acc[8]) {
    stageAW(scratch, A2g, Wg, 0, tid);
    cp_commit();
    for (int c = 0; c < 8; c++) {
        if (c < 7) { stageAW(scratch + ((c + 1) & 1) * ABUFF, A2g, Wg, c + 1, tid); cp_commit(); cp_wait1(); }
        else cp_wait0();
        __syncthreads();
        const float* Ab = scratch + (c & 1) * ABUFF;
        const float* Ap = Ab + bq * ASTRIDE + kg * 8;
        const float* Wp = Ab + (16 + ccq) * ASTRIDE + kg * 8;
#pragma unroll
        for (int q = 0; q < 2; q++) {
            ulonglong2 a0 = *(const ulonglong2*)(Ap + q * 4);
            ulonglong2 a1 = *(const ulonglong2*)(Ap + 8 * ASTRIDE + q * 4);
            ulonglong2 w0 = *(const ulonglong2*)(Wp + q * 4);
            ulonglong2 w1 = *(const ulonglong2*)(Wp + 4 * ASTRIDE + q * 4);
            ulonglong2 w2 = *(const ulonglong2*)(Wp + 8 * ASTRIDE + q * 4);
            ulonglong2 w3 = *(const ulonglong2*)(Wp + 12 * ASTRIDE + q * 4);
            ffma2(acc[0], a0.x, w0.x); ffma2(acc[0], a0.y, w0.y);
            ffma2(acc[1], a0.x, w1.x); ffma2(acc[1], a0.y, w1.y);
            ffma2(acc[2], a0.x, w2.x); ffma2(acc[2], a0.y, w2.y);
            ffma2(acc[3], a0.x, w3.x); ffma2(acc[3], a0.y, w3.y);
            ffma2(acc[4], a1.x, w0.x); ffma2(acc[4], a1.y, w0.y);
            ffma2(acc[5], a1.x, w1.x); ffma2(acc[5], a1.y, w1.y);
            ffma2(acc[6], a1.x, w2.x); ffma2(acc[6], a1.y, w2.y);
            ffma2(acc[7], a1.x, w3.x); ffma2(acc[7], a1.y, w3.y);
        }
        __syncthreads();
    }
}

__device__ __forceinline__ void gridbar(unsigned int gen) {
    __syncthreads();
    if (threadIdx.x == 0) {
        __threadfence();
        atomicAdd(&g_bar, 1u);
        const unsigned int target = gen * NCTA;
        while (*(volatile unsigned int*)&g_bar < target) { __nanosleep(32); }
        __threadfence();
    }
    __syncthreads();
}

// ---------------- persistent recurrent kernel ----------------
// 128 CTAs x 512 threads. CTA i owns h-tile rows b0..b0+31 x cols c0..c0+15 and
// out-tile rows bo0..bo0+15 x cols co0..co0+15.
// Producers: bq=tid&7, ccq=(tid>>3)&3, kg=tid>>5 (16-way warp-uniform K split).
// Reduction: red[kg*545 + ls*17 + z] (conflict-free both directions).
// Finalizers: thread tid = zz*32 + ls handles acc-slot zz of lane ls.
__global__ void __launch_bounds__(NTHR, 1) rnn_persist(
    const float* __restrict__ W_hh0, const float* __restrict__ b_hh0,
    const float* __restrict__ W_ih1, const float* __restrict__ b_ih1,
    const float* __restrict__ W_hh1, const float* __restrict__ b_hh1,
    const float* __restrict__ W_out, const float* __restrict__ b_out,
    float* __restrict__ out) {
    extern __shared__ __align__(16) float Wsm[];
    float* scratch = Wsm + 3 * WT;     // staging buffers AND reduction scratch (aliased)
    float* red     = scratch;

    const int tid = threadIdx.x;
    const int bq  = tid & 7;
    const int ccq = (tid >> 3) & 3;
    const int kg  = tid >> 5;          // 0..15, warp-uniform
    const int ls  = tid & 31;
    const int zz  = tid >> 5;          // finalizer slot
    const int i   = blockIdx.x;
    const int b0 = (i & 1) * 32, c0 = (i >> 1) * 16;
    const int bo0 = (i & 3) * 16, co0 = (i >> 2) * 16;

    // finalizer coordinates (h: 512 outputs; out: 256 outputs, tid<256)
    const int hrow = (ls & 7) + 8 * (zz >> 2);
    const int hcol = (ls >> 3) + 4 * (zz & 3);
    const int orow = (ls & 7) + 8 * (zz >> 2);   // valid for zz<8
    const int ocol = (ls >> 3) + 4 * (zz & 3);

    // ---- one-time weight preload, quad-swizzled: addr = r*1024 + 4*(quad ^ (r&3)) ----
    {
        const float* s0 = W_hh0 + (size_t)c0 * Hh;
        const float* s1 = W_ih1 + (size_t)c0 * Hh;
        const float* s2 = W_hh1 + (size_t)c0 * Hh;
        for (int idx = tid; idx < 16 * 256; idx += NTHR) {
            int r = idx >> 8, qi = idx & 255;
            int dsto = r * 1024 + ((qi ^ (r & 3)) << 2);
            *(float4*)&Wsm[dsto]          = *(const float4*)(s0 + (size_t)r * Hh + qi * 4);
            *(float4*)&Wsm[WT + dsto]     = *(const float4*)(s1 + (size_t)r * Hh + qi * 4);
            *(float4*)&Wsm[2 * WT + dsto] = *(const float4*)(s2 + (size_t)r * Hh + qi * 4);
        }
    }
    const float biasH0 = __ldg(b_hh0 + c0 + hcol);
    const float biasH1 = __ldg(b_ih1 + c0 + hcol) + __ldg(b_hh1 + c0 + hcol);
    const float biasO  = __ldg(b_out + co0 + ocol);
    const float* WoG = W_out + (size_t)co0 * Hh;   // 16-row slab, streamed per step
    __syncthreads();

    int p = 0;
    unsigned int gen = 0;

    for (int t = 0; t < Tt; t++) {
        // ================= Phase 1: h0n(t) + out(t-1) =================
        float x = __ldcs(g_xp + ((size_t)(t * Bb + b0 + hrow)) * Hh + c0 + hcol);

        u64 accH[16];
#pragma unroll
        for (int z = 0; z < 16; z++) accH[z] = 0ull;
        dot44(g_h0[p] + (size_t)b0 * Hh, Wsm, scratch, tid, bq, ccq, kg, accH);

#pragma unroll
        for (int z = 0; z < 16; z++) red[kg * 545 + ls * 17 + z] = redsum(accH[z]);
        __syncthreads();
        {
            float s = 0.f;
#pragma unroll
            for (int w = 0; w < 16; w++) s += red[w * 545 + ls * 17 + zz];
            __stcg(g_h0[1 - p] + (size_t)(b0 + hrow) * Hh + c0 + hcol,
                   tanhf(s + x + biasH0));
        }
        __syncthreads();                       // gather reads done before scratch reuse

        if (t > 0) {                           // uniform condition: bars inside are safe
            u64 accO[8];
#pragma unroll
            for (int z = 0; z < 8; z++) accO[z] = 0ull;
            dot24(g_h1[p] + (size_t)bo0 * Hh, WoG, scratch, tid, bq, ccq, kg, accO);
#pragma unroll
            for (int z = 0; z < 8; z++) red[kg * 545 + ls * 17 + z] = redsum(accO[z]);
            __syncthreads();
            if (tid < 256) {
                float s = 0.f;
#pragma unroll
                for (int w = 0; w < 16; w++) s += red[w * 545 + ls * 17 + zz];
                out[((size_t)(bo0 + orow) * Tt + (t - 1)) * Oo + co0 + ocol] = s + biasO;
            }
        }
        gridbar(++gen);

        // ================= Phase 2: h1n(t) = tanh(h0n@W_ih1^T + h1@W_hh1^T + b) =====
        {
            u64 acc[16];
#pragma unroll
            for (int z = 0; z < 16; z++) acc[z] = 0ull;
            dot44(g_h0[1 - p] + (size_t)b0 * Hh, Wsm + WT,     scratch, tid, bq, ccq, kg, acc);
            dot44(g_h1[p]     + (size_t)b0 * Hh, Wsm + 2 * WT, scratch, tid, bq, ccq, kg, acc);

#pragma unroll
            for (int z = 0; z < 16; z++) red[kg * 545 + ls * 17 + z] = redsum(acc[z]);
            __syncthreads();
            float s = 0.f;
#pragma unroll
            for (int w = 0; w < 16; w++) s += red[w * 545 + ls * 17 + zz];
            __stcg(g_h1[1 - p] + (size_t)(b0 + hrow) * Hh + c0 + hcol,
                   tanhf(s + biasH1));
        }
        gridbar(++gen);
        p ^= 1;
    }

    // ================= tail: out(T-1) from final h1 =================
    {
        u64 accO[8];
#pragma unroll
        for (int z = 0; z < 8; z++) accO[z] = 0ull;
        dot24(g_h1[p] + (size_t)bo0 * Hh, WoG, scratch, tid, bq, ccq, kg, accO);
#pragma unroll
        for (int z = 0; z < 8; z++) red[kg * 545 + ls * 17 + z] = redsum(accO[z]);
        __syncthreads();
        if (tid < 256) {
            float s = 0.f;
#pragma unroll
            for (int w = 0; w < 16; w++) s += red[w * 545 + ls * 17 + zz];
            out[((size_t)(bo0 + orow) * Tt + (Tt - 1)) * Oo + co0 + ocol] = s + biasO;
        }
    }
}

// ---------------- launch ----------------
extern "C" void kernel_launch(void* const* d_in, const int* in_sizes, int n_in,
                              void* d_out, int out_size) {
    const float* emb   = (const float*)d_in[0];
    const float* h0    = (const float*)d_in[1];
    const float* W_ih0 = (const float*)d_in[2];
    const float* b_ih0 = (const float*)d_in[3];
    const float* W_ih1 = (const float*)d_in[4];
    const float* b_ih1 = (const float*)d_in[5];
    const float* W_hh0 = (const float*)d_in[6];
    const float* b_hh0 = (const float*)d_in[7];
    const float* W_hh1 = (const float*)d_in[8];
    const float* b_hh1 = (const float*)d_in[9];
    const float* W_out = (const float*)d_in[10];
    const float* b_out = (const float*)d_in[11];
    float* out = (float*)d_out;

    // unconditional (no static guards per harness contract); host-side, capture-safe
    cudaFuncSetAttribute(rnn_persist, cudaFuncAttributeMaxDynamicSharedMemorySize, SMEM_BYTES);

    init_kernel<<<128, 256>>>(h0);
    xp_gemm<<<dim3(Hh / 64, (Tt * Bb) / 128), 256>>>(emb, W_ih0, b_ih0);
    rnn_persist<<<NCTA, NTHR, SMEM_BYTES>>>(W_hh0, b_hh0, W_ih1, b_ih1, W_hh1, b_hh1,
                                            W_out, b_out, out);
}

// round 17
// speedup vs baseline: 16.1386x; 1.0708x over previous
#include <cuda_runtime.h>
#include <cstdint>

#define Tt 512
#define Bb 64
#define Ee 512
#define Hh 1024
#define Oo 512
#define NCTA 128
#define NTHR 512
#define WT 16384                 // floats per 16-row swizzled weight slice (16*1024)
#define ASTRIDE 132              // floats; 128+4 pad for A staging rows
#define ABUFF (32 * ASTRIDE)     // 4224 floats per staging buffer
#define REDSZ (16 * 545)         // 8720 floats reduction scratch (overlaps staging)
#define SMEM_FLOATS (3 * WT + REDSZ)
#define SMEM_BYTES (SMEM_FLOATS * 4)   // 231,488 B <= 232,448 cap

typedef unsigned long long u64;

// ---------------- device scratch ----------------
__device__ float g_xp[Tt * Bb * Hh];      // (t, b, h) input projections
__device__ float g_h0[2][Bb * Hh];        // layer-0 hidden ping-pong
__device__ float g_h1[3][Bb * Hh];        // layer-1 hidden TRIPLE buffer (post-arrival reads)
__device__ unsigned int g_flags[NCTA * 8];// per-CTA arrival flags (32B padded)

// ---------------- packed f32x2 helpers ----------------
__device__ __forceinline__ void ffma2(u64& d, u64 a, u64 b) {
    asm("fma.rn.f32x2 %0, %1, %2, %0;" : "+l"(d) : "l"(a), "l"(b));
}
__device__ __forceinline__ u64 pack2(float x, float y) {
    u64 r; asm("mov.b64 %0, {%1, %2};" : "=l"(r) : "f"(x), "f"(y)); return r;
}
__device__ __forceinline__ float2 unpack2(u64 v) {
    float2 f; asm("mov.b64 {%0, %1}, %2;" : "=f"(f.x), "=f"(f.y) : "l"(v)); return f;
}
__device__ __forceinline__ float redsum(u64 v) {
    float2 f = unpack2(v); return f.x + f.y;
}

// ---------------- cp.async helpers (.cg = L2-only: ping-pong coherence) ----------
__device__ __forceinline__ void cpasync16(void* sdst, const void* gsrc) {
    unsigned s = (unsigned)__cvta_generic_to_shared(sdst);
    asm volatile("cp.async.cg.shared.global [%0], [%1], 16;" :: "r"(s), "l"(gsrc));
}
__device__ __forceinline__ void cp_commit() { asm volatile("cp.async.commit_group;"); }
__device__ __forceinline__ void cp_wait1()  { asm volatile("cp.async.wait_group 1;"); }
__device__ __forceinline__ void cp_wait0()  { asm volatile("cp.async.wait_group 0;"); }

// ---------------- init ----------------
__global__ void init_kernel(const float* __restrict__ h0in) {
    int idx = blockIdx.x * blockDim.x + threadIdx.x;
    if (idx < NCTA * 8) g_flags[idx] = 0u;
    for (int i = idx; i < Bb * Hh; i += gridDim.x * blockDim.x) {
        g_h0[0][i] = h0in[i];
        g_h1[0][i] = h0in[Bb * Hh + i];
    }
}

// ---------------- xp = embeddings @ W_ih0^T + b_ih0, stored (t,b,h) ----------------
__global__ __launch_bounds__(256) void xp_gemm(const float* __restrict__ emb,
                                               const float* __restrict__ W,
                                               const float* __restrict__ bias) {
    __shared__ __align__(16) float As[16 * 132];
    __shared__ __align__(16) float Bs[16 * 68];
    const int tid = threadIdx.x;
    const int tx = tid & 15;
    const int ty = tid >> 4;
    const int m0 = blockIdx.y * 128;
    const int n0 = blockIdx.x * 64;

    u64 acc[4][4];
#pragma unroll
    for (int i = 0; i < 4; i++)
#pragma unroll
        for (int j = 0; j < 4; j++) acc[i][j] = 0ull;

    for (int k0 = 0; k0 < Ee; k0 += 16) {
#pragma unroll
        for (int rep = 0; rep < 2; rep++) {
            int f = tid + rep * 256;
            int m_l = f >> 2, kk = (f & 3) * 4;
            int m = m0 + m_l;
            int b = m & 63, t = m >> 6;
            const float4 v = *(const float4*)(emb + ((size_t)b * Tt + t) * Ee + k0 + kk);
            As[(kk + 0) * 132 + m_l] = v.x;
            As[(kk + 1) * 132 + m_l] = v.y;
            As[(kk + 2) * 132 + m_l] = v.z;
            As[(kk + 3) * 132 + m_l] = v.w;
        }
        {
            int n_l = tid >> 2, kk = (tid & 3) * 4;
            const float4 v = *(const float4*)(W + (size_t)(n0 + n_l) * Ee + k0 + kk);
            Bs[(kk + 0) * 68 + n_l] = v.x;
            Bs[(kk + 1) * 68 + n_l] = v.y;
            Bs[(kk + 2) * 68 + n_l] = v.z;
            Bs[(kk + 3) * 68 + n_l] = v.w;
        }
        __syncthreads();
#pragma unroll
        for (int k = 0; k < 16; k++) {
            ulonglong2 aA = *(const ulonglong2*)&As[k * 132 + ty * 8];
            ulonglong2 aB = *(const ulonglong2*)&As[k * 132 + ty * 8 + 4];
            float4 bv = *(const float4*)&Bs[k * 68 + tx * 4];
            u64 bd0 = pack2(bv.x, bv.x);
            u64 bd1 = pack2(bv.y, bv.y);
            u64 bd2 = pack2(bv.z, bv.z);
            u64 bd3 = pack2(bv.w, bv.w);
            ffma2(acc[0][0], aA.x, bd0); ffma2(acc[0][1], aA.x, bd1);
            ffma2(acc[0][2], aA.x, bd2); ffma2(acc[0][3], aA.x, bd3);
            ffma2(acc[1][0], aA.y, bd0); ffma2(acc[1][1], aA.y, bd1);
            ffma2(acc[1][2], aA.y, bd2); ffma2(acc[1][3], aA.y, bd3);
            ffma2(acc[2][0], aB.x, bd0); ffma2(acc[2][1], aB.x, bd1);
            ffma2(acc[2][2], aB.x, bd2); ffma2(acc[2][3], aB.x, bd3);
            ffma2(acc[3][0], aB.y, bd0); ffma2(acc[3][1], aB.y, bd1);
            ffma2(acc[3][2], aB.y, bd2); ffma2(acc[3][3], aB.y, bd3);
        }
        __syncthreads();
    }
#pragma unroll
    for (int i2 = 0; i2 < 4; i2++) {
#pragma unroll
        for (int j = 0; j < 4; j++) {
            float2 v = unpack2(acc[i2][j]);
            int m = m0 + ty * 8 + i2 * 2;
            int n = n0 + tx * 4 + j;
            float bb = bias[n];
            g_xp[(size_t)m * Hh + n]       = v.x + bb;
            g_xp[(size_t)(m + 1) * Hh + n] = v.y + bb;
        }
    }
}

// ---------------- staging (512 threads): 32 rows x 128 k, 16B cp.async ----------
__device__ __forceinline__ void stageA32(float* dst, const float* __restrict__ Ag,
                                         int chunk, int tid) {
#pragma unroll
    for (int i = 0; i < 2; i++) {
        int idx = tid + i * 512;
        int row = idx >> 5, kq = idx & 31;
        cpasync16(dst + row * ASTRIDE + kq * 4,
                  Ag + (size_t)row * Hh + chunk * 128 + kq * 4);
    }
}
// rows 0-15 = A tile (16 rows), rows 16-31 = streamed W slab (16 rows)
__device__ __forceinline__ void stageAW(float* dst, const float* __restrict__ A2g,
                                        const float* __restrict__ Wg, int chunk, int tid) {
    {
        int row = tid >> 5, kq = tid & 31;
        cpasync16(dst + row * ASTRIDE + kq * 4,
                  A2g + (size_t)row * Hh + chunk * 128 + kq * 4);
        cpasync16(dst + (16 + row) * ASTRIDE + kq * 4,
                  Wg + (size_t)row * Hh + chunk * 128 + kq * 4);
    }
}

// ---------------- 4x4 tile dot: 32 rows x 16 cols x K=1024, W swizzled in smem ---
__device__ __forceinline__ void dot44(const float* __restrict__ Ag,
                                      const float* __restrict__ Wslice,
                                      float* scratch, int tid, int bq, int ccq, int kg,
                                      u64 acc[16]) {
    stageA32(scratch, Ag, 0, tid);
    cp_commit();
    for (int c = 0; c < 8; c++) {
        if (c < 7) { stageA32(scratch + ((c + 1) & 1) * ABUFF, Ag, c + 1, tid); cp_commit(); cp_wait1(); }
        else cp_wait0();
        __syncthreads();
        const float* Ap = scratch + (c & 1) * ABUFF + bq * ASTRIDE + kg * 8;
        const float* Wb = Wslice + ccq * 1024;
        const int qb = c * 32 + kg * 2;
#pragma unroll
        for (int q = 0; q < 2; q++) {
            const int wq = ((qb + q) ^ ccq) << 2;        // quad swizzle (key = row&3 = ccq)
            ulonglong2 w0 = *(const ulonglong2*)(Wb + wq);
            ulonglong2 w1 = *(const ulonglong2*)(Wb + 4096 + wq);
            ulonglong2 w2 = *(const ulonglong2*)(Wb + 8192 + wq);
            ulonglong2 w3 = *(const ulonglong2*)(Wb + 12288 + wq);
            ulonglong2 a0 = *(const ulonglong2*)(Ap + q * 4);
            ulonglong2 a1 = *(const ulonglong2*)(Ap + 8 * ASTRIDE + q * 4);
            ulonglong2 a2 = *(const ulonglong2*)(Ap + 16 * ASTRIDE + q * 4);
            ulonglong2 a3 = *(const ulonglong2*)(Ap + 24 * ASTRIDE + q * 4);
            ffma2(acc[ 0], a0.x, w0.x); ffma2(acc[ 0], a0.y, w0.y);
            ffma2(acc[ 1], a0.x, w1.x); ffma2(acc[ 1], a0.y, w1.y);
            ffma2(acc[ 2], a0.x, w2.x); ffma2(acc[ 2], a0.y, w2.y);
            ffma2(acc[ 3], a0.x, w3.x); ffma2(acc[ 3], a0.y, w3.y);
            ffma2(acc[ 4], a1.x, w0.x); ffma2(acc[ 4], a1.y, w0.y);
            ffma2(acc[ 5], a1.x, w1.x); ffma2(acc[ 5], a1.y, w1.y);
            ffma2(acc[ 6], a1.x, w2.x); ffma2(acc[ 6], a1.y, w2.y);
            ffma2(acc[ 7], a1.x, w3.x); ffma2(acc[ 7], a1.y, w3.y);
            ffma2(acc[ 8], a2.x, w0.x); ffma2(acc[ 8], a2.y, w0.y);
            ffma2(acc[ 9], a2.x, w1.x); ffma2(acc[ 9], a2.y, w1.y);
            ffma2(acc[10], a2.x, w2.x); ffma2(acc[10], a2.y, w2.y);
            ffma2(acc[11], a2.x, w3.x); ffma2(acc[11], a2.y, w3.y);
            ffma2(acc[12], a3.x, w0.x); ffma2(acc[12], a3.y, w0.y);
            ffma2(acc[13], a3.x, w1.x); ffma2(acc[13], a3.y, w1.y);
            ffma2(acc[14], a3.x, w2.x); ffma2(acc[14], a3.y, w2.y);
            ffma2(acc[15], a3.x, w3.x); ffma2(acc[15], a3.y, w3.y);
        }
        __syncthreads();
    }
}

// ---------------- 2x4 tile out-dot: 16 rows x 16 cols x K=1024, W streamed -------
__device__ __forceinline__ void dot24(const float* __restrict__ A2g,
                                      const float* __restrict__ Wg,
                                      float* scratch, int tid, int bq, int ccq, int kg,
                                      u64 acc[8]) {
    stageAW(scratch, A2g, Wg, 0, tid);
    cp_commit();
    for (int c = 0; c < 8; c++) {
        if (c < 7) { stageAW(scratch + ((c + 1) & 1) * ABUFF, A2g, Wg, c + 1, tid); cp_commit(); cp_wait1(); }
        else cp_wait0();
        __syncthreads();
        const float* Ab = scratch + (c & 1) * ABUFF;
        const float* Ap = Ab + bq * ASTRIDE + kg * 8;
        const float* Wp = Ab + (16 + ccq) * ASTRIDE + kg * 8;
#pragma unroll
        for (int q = 0; q < 2; q++) {
            ulonglong2 a0 = *(const ulonglong2*)(Ap + q * 4);
            ulonglong2 a1 = *(const ulonglong2*)(Ap + 8 * ASTRIDE + q * 4);
            ulonglong2 w0 = *(const ulonglong2*)(Wp + q * 4);
            ulonglong2 w1 = *(const ulonglong2*)(Wp + 4 * ASTRIDE + q * 4);
            ulonglong2 w2 = *(const ulonglong2*)(Wp + 8 * ASTRIDE + q * 4);
            ulonglong2 w3 = *(const ulonglong2*)(Wp + 12 * ASTRIDE + q * 4);
            ffma2(acc[0], a0.x, w0.x); ffma2(acc[0], a0.y, w0.y);
            ffma2(acc[1], a0.x, w1.x); ffma2(acc[1], a0.y, w1.y);
            ffma2(acc[2], a0.x, w2.x); ffma2(acc[2], a0.y, w2.y);
            ffma2(acc[3], a0.x, w3.x); ffma2(acc[3], a0.y, w3.y);
            ffma2(acc[4], a1.x, w0.x); ffma2(acc[4], a1.y, w0.y);
            ffma2(acc[5], a1.x, w1.x); ffma2(acc[5], a1.y, w1.y);
            ffma2(acc[6], a1.x, w2.x); ffma2(acc[6], a1.y, w2.y);
            ffma2(acc[7], a1.x, w3.x); ffma2(acc[7], a1.y, w3.y);
        }
        __syncthreads();
    }
}

// ---------------- flag barrier (parallel arrivals, distinct addresses) -----------
// arrive: after a __syncthreads that closes all this-phase h-stores.
__device__ __forceinline__ void bar_arrive(unsigned int gen) {
    if (threadIdx.x == 0) {
        __threadfence();   // release this CTA's h-state stores
        *(volatile unsigned int*)&g_flags[blockIdx.x * 8] = gen;
    }
}
__device__ __forceinline__ void bar_wait(unsigned int gen) {
    if (threadIdx.x < NCTA) {
        while (*(volatile unsigned int*)&g_flags[threadIdx.x * 8] < gen) { __nanosleep(32); }
        __threadfence();   // acquire
    }
    __syncthreads();
}

// ---------------- persistent recurrent kernel (wavefront over (t, layer)) --------
// Phase t: h0n(t) [t<T], h1n(t-1) [t>=1], out(t-2) [t>=2, computed AFTER arrival,
// hidden in the barrier wait]. ONE barrier per phase (513 total).
// Buffers: h0(t) in g_h0[(t+1)&1] (double); h1(t) in g_h1[(t+1)%3] (triple — the
// post-arrival out-read of h1(t-2) is 2 barrier generations from its overwrite).
__global__ void __launch_bounds__(NTHR, 1) rnn_persist(
    const float* __restrict__ W_hh0, const float* __restrict__ b_hh0,
    const float* __restrict__ W_ih1, const float* __restrict__ b_ih1,
    const float* __restrict__ W_hh1, const float* __restrict__ b_hh1,
    const float* __restrict__ W_out, const float* __restrict__ b_out,
    float* __restrict__ out) {
    extern __shared__ __align__(16) float Wsm[];
    float* scratch = Wsm + 3 * WT;     // staging buffers AND reduction scratch (aliased)
    float* red     = scratch;

    const int tid = threadIdx.x;
    const int bq  = tid & 7;
    const int ccq = (tid >> 3) & 3;
    const int kg  = tid >> 5;          // 0..15, warp-uniform
    const int ls  = tid & 31;
    const int zz  = tid >> 5;          // finalizer slot
    const int i   = blockIdx.x;
    const int b0 = (i & 1) * 32, c0 = (i >> 1) * 16;
    const int bo0 = (i & 3) * 16, co0 = (i >> 2) * 16;

    // finalizer coordinates (h: 512 outputs; out: 256 outputs, tid<256)
    const int hrow = (ls & 7) + 8 * (zz >> 2);
    const int hcol = (ls >> 3) + 4 * (zz & 3);
    const int orow = (ls & 7) + 8 * (zz >> 2);   // valid for zz<8
    const int ocol = (ls >> 3) + 4 * (zz & 3);

    // ---- one-time weight preload, quad-swizzled: addr = r*1024 + 4*(quad ^ (r&3)) ----
    {
        const float* s0 = W_hh0 + (size_t)c0 * Hh;
        const float* s1 = W_ih1 + (size_t)c0 * Hh;
        const float* s2 = W_hh1 + (size_t)c0 * Hh;
        for (int idx = tid; idx < 16 * 256; idx += NTHR) {
            int r = idx >> 8, qi = idx & 255;
            int dsto = r * 1024 + ((qi ^ (r & 3)) << 2);
            *(float4*)&Wsm[dsto]          = *(const float4*)(s0 + (size_t)r * Hh + qi * 4);
            *(float4*)&Wsm[WT + dsto]     = *(const float4*)(s1 + (size_t)r * Hh + qi * 4);
            *(float4*)&Wsm[2 * WT + dsto] = *(const float4*)(s2 + (size_t)r * Hh + qi * 4);
        }
    }
    const float biasH0 = __ldg(b_hh0 + c0 + hcol);
    const float biasH1 = __ldg(b_ih1 + c0 + hcol) + __ldg(b_hh1 + c0 + hcol);
    const float biasO  = __ldg(b_out + co0 + ocol);
    const float* WoG = W_out + (size_t)co0 * Hh;   // 16-row slab, streamed per phase
    __syncthreads();

    for (int t = 0; t < Tt; t++) {
        const int p0r = t & 1;          // h0(t-1) buffer
        const int h1w = t % 3;          // h1(t-1) write buffer
        const int h1r = (t + 2) % 3;    // h1(t-2) read buffer

        // ---- h0n(t) = tanh(xp(t) + h0(t-1) @ W_hh0^T + b) ----
        float x = __ldcs(g_xp + ((size_t)(t * Bb + b0 + hrow)) * Hh + c0 + hcol);
        {
            u64 accH[16];
#pragma unroll
            for (int z = 0; z < 16; z++) accH[z] = 0ull;
            dot44(g_h0[p0r] + (size_t)b0 * Hh, Wsm, scratch, tid, bq, ccq, kg, accH);
#pragma unroll
            for (int z = 0; z < 16; z++) red[kg * 545 + ls * 17 + z] = redsum(accH[z]);
            __syncthreads();
            float s = 0.f;
#pragma unroll
            for (int w = 0; w < 16; w++) s += red[w * 545 + ls * 17 + zz];
            __stcg(g_h0[1 - p0r] + (size_t)(b0 + hrow) * Hh + c0 + hcol,
                   tanhf(s + x + biasH0));
            __syncthreads();           // gather reads done before scratch reuse
        }

        // ---- h1n(t-1) = tanh(h0(t-1)@W_ih1^T + h1(t-2)@W_hh1^T + b) ----
        if (t >= 1) {
            u64 acc[16];
#pragma unroll
            for (int z = 0; z < 16; z++) acc[z] = 0ull;
            dot44(g_h0[p0r] + (size_t)b0 * Hh, Wsm + WT,     scratch, tid, bq, ccq, kg, acc);
            dot44(g_h1[h1r] + (size_t)b0 * Hh, Wsm + 2 * WT, scratch, tid, bq, ccq, kg, acc);
#pragma unroll
            for (int z = 0; z < 16; z++) red[kg * 545 + ls * 17 + z] = redsum(acc[z]);
            __syncthreads();
            float s = 0.f;
#pragma unroll
            for (int w = 0; w < 16; w++) s += red[w * 545 + ls * 17 + zz];
            __stcg(g_h1[h1w] + (size_t)(b0 + hrow) * Hh + c0 + hcol,
                   tanhf(s + biasH1));
            __syncthreads();           // closes all h-stores of this phase
        }

        // ---- arrive, then compute out(t-2) inside the wait window ----
        bar_arrive(t + 1u);
        if (t >= 2) {
            u64 accO[8];
#pragma unroll
            for (int z = 0; z < 8; z++) accO[z] = 0ull;
            dot24(g_h1[h1r] + (size_t)bo0 * Hh, WoG, scratch, tid, bq, ccq, kg, accO);
#pragma unroll
            for (int z = 0; z < 8; z++) red[kg * 545 + ls * 17 + z] = redsum(accO[z]);
            __syncthreads();
            if (tid < 256) {
                float s = 0.f;
#pragma unroll
                for (int w = 0; w < 16; w++) s += red[w * 545 + ls * 17 + zz];
                out[((size_t)(bo0 + orow) * Tt + (t - 2)) * Oo + co0 + ocol] = s + biasO;
            }
            __syncthreads();           // red reads done before next phase's staging
        }
        bar_wait(t + 1u);
    }

    // ================= post-loop phase (t = Tt): h1n(T-1) + out(T-2) =================
    {
        const int t = Tt;
        const int p0r = t & 1;
        const int h1w = t % 3;          // 512%3 = 2
        const int h1r = (t + 2) % 3;    // = 1
        {
            u64 acc[16];
#pragma unroll
            for (int z = 0; z < 16; z++) acc[z] = 0ull;
            dot44(g_h0[p0r] + (size_t)b0 * Hh, Wsm + WT,     scratch, tid, bq, ccq, kg, acc);
            dot44(g_h1[h1r] + (size_t)b0 * Hh, Wsm + 2 * WT, scratch, tid, bq, ccq, kg, acc);
#pragma unroll
            for (int z = 0; z < 16; z++) red[kg * 545 + ls * 17 + z] = redsum(acc[z]);
            __syncthreads();
            float s = 0.f;
#pragma unroll
            for (int w = 0; w < 16; w++) s += red[w * 545 + ls * 17 + zz];
            __stcg(g_h1[h1w] + (size_t)(b0 + hrow) * Hh + c0 + hcol,
                   tanhf(s + biasH1));
            __syncthreads();
        }
        bar_arrive(t + 1u);
        {
            u64 accO[8];
#pragma unroll
            for (int z = 0; z < 8; z++) accO[z] = 0ull;
            dot24(g_h1[h1r] + (size_t)bo0 * Hh, WoG, scratch, tid, bq, ccq, kg, accO);
#pragma unroll
            for (int z = 0; z < 8; z++) red[kg * 545 + ls * 17 + z] = redsum(accO[z]);
            __syncthreads();
            if (tid < 256) {
                float s = 0.f;
#pragma unroll
                for (int w = 0; w < 16; w++) s += red[w * 545 + ls * 17 + zz];
                out[((size_t)(bo0 + orow) * Tt + (Tt - 2)) * Oo + co0 + ocol] = s + biasO;
            }
            __syncthreads();
        }
        bar_wait(t + 1u);
    }

    // ================= final: out(T-1) from h1(T-1) (no barrier after) =================
    {
        u64 accO[8];
#pragma unroll
        for (int z = 0; z < 8; z++) accO[z] = 0ull;
        dot24(g_h1[Tt % 3] + (size_t)bo0 * Hh, WoG, scratch, tid, bq, ccq, kg, accO);
#pragma unroll
        for (int z = 0; z < 8; z++) red[kg * 545 + ls * 17 + z] = redsum(accO[z]);
        __syncthreads();
        if (tid < 256) {
            float s = 0.f;
#pragma unroll
            for (int w = 0; w < 16; w++) s += red[w * 545 + ls * 17 + zz];
            out[((size_t)(bo0 + orow) * Tt + (Tt - 1)) * Oo + co0 + ocol] = s + biasO;
        }
    }
}

// ---------------- launch ----------------
extern "C" void kernel_launch(void* const* d_in, const int* in_sizes, int n_in,
                              void* d_out, int out_size) {
    const float* emb   = (const float*)d_in[0];
    const float* h0    = (const float*)d_in[1];
    const float* W_ih0 = (const float*)d_in[2];
    const float* b_ih0 = (const float*)d_in[3];
    const float* W_ih1 = (const float*)d_in[4];
    const float* b_ih1 = (const float*)d_in[5];
    const float* W_hh0 = (const float*)d_in[6];
    const float* b_hh0 = (const float*)d_in[7];
    const float* W_hh1 = (const float*)d_in[8];
    const float* b_hh1 = (const float*)d_in[9];
    const float* W_out = (const float*)d_in[10];
    const float* b_out = (const float*)d_in[11];
    float* out = (float*)d_out;

    // unconditional (no static guards per harness contract); host-side, capture-safe
    cudaFuncSetAttribute(rnn_persist, cudaFuncAttributeMaxDynamicSharedMemorySize, SMEM_BYTES);

    init_kernel<<<128, 256>>>(h0);
    xp_gemm<<<dim3(Hh / 64, (Tt * Bb) / 128), 256>>>(emb, W_ih0, b_ih0);
    rnn_persist<<<NCTA, NTHR, SMEM_BYTES>>>(W_hh0, b_hh0, W_ih1, b_ih1, W_hh1, b_hh1,
                                            W_out, b_out, out);
}